// round 1
// baseline (speedup 1.0000x reference)
#include <cuda_runtime.h>
#include <math.h>

// Problem constants (fixed shapes from the reference)
#define NTOK 4096     // B*S = 2*2048
#define HD   1024     // hidden
#define NE   8        // experts
#define FD   4096     // ffn dim
#define NSLOT (NTOK * 2)   // top-2 -> exactly 8192 assignments

// GEMM tiling
#define BM 128
#define BN 128
#define BK 16
#define PADA 4        // As row pad: ld = BK+4 = 20 floats (conflict-free frag reads)
#define PADB 8        // Bs row pad: ld = BN+8 = 136 floats

// ---------------- scratch (device globals; no allocation in kernel_launch) ---
__device__ float g_h[(size_t)NSLOT * FD];   // gelu(x@W1+b1) per assignment  (128MB)
__device__ float g_y[(size_t)NSLOT * HD];   // h@W2 per assignment           (32MB)
__device__ int   g_tok_of_slot[NSLOT];
__device__ int   g_slot_of_tok[NSLOT];      // [token*2 + k]
__device__ int   g_expert_of_tok[NSLOT];    // [token*2 + k]
__device__ float g_gate_of_tok[NSLOT];      // [token*2 + k]
__device__ int   g_counts[NE];
__device__ int   g_offsets[NE + 1];

// ---------------- helpers ---------------------------------------------------
__device__ __forceinline__ float tf32r(float f) {
    unsigned u;
    asm("cvt.rna.tf32.f32 %0, %1;" : "=r"(u) : "f"(f));
    return __uint_as_float(u);
}

__device__ __forceinline__ float4 tf32x4(float4 v) {
    return make_float4(tf32r(v.x), tf32r(v.y), tf32r(v.z), tf32r(v.w));
}

__device__ __forceinline__ void mma8(float c[4],
                                     unsigned a0, unsigned a1, unsigned a2, unsigned a3,
                                     unsigned b0, unsigned b1) {
    asm volatile(
        "mma.sync.aligned.m16n8k8.row.col.f32.tf32.tf32.f32 "
        "{%0,%1,%2,%3}, {%4,%5,%6,%7}, {%8,%9}, {%0,%1,%2,%3};\n"
        : "+f"(c[0]), "+f"(c[1]), "+f"(c[2]), "+f"(c[3])
        : "r"(a0), "r"(a1), "r"(a2), "r"(a3), "r"(b0), "r"(b1));
}

__device__ __forceinline__ float gelu_exact(float x) {
    return 0.5f * x * (1.0f + erff(x * 0.70710678118654752440f));
}

// ---------------- stage 0: zero counts --------------------------------------
__global__ void init_kernel() {
    if (threadIdx.x < NE) g_counts[threadIdx.x] = 0;
}

// ---------------- stage 1: router (logits, top-2, softmax) ------------------
__global__ void router_kernel(const float* __restrict__ x,
                              const float* __restrict__ Wr) {
    const int t = blockIdx.x;
    __shared__ float sx[HD];
    __shared__ float slog[NE];

    const float* xr = x + (size_t)t * HD;
    for (int i = threadIdx.x; i < HD; i += blockDim.x) sx[i] = xr[i];
    __syncthreads();

    const int w = threadIdx.x >> 5, lane = threadIdx.x & 31;
    if (w < NE) {
        const float* wr = Wr + (size_t)w * HD;
        float s = 0.f;
        for (int i = lane; i < HD; i += 32) s += sx[i] * wr[i];
        #pragma unroll
        for (int o = 16; o > 0; o >>= 1) s += __shfl_xor_sync(0xffffffffu, s, o);
        if (lane == 0) slog[w] = s;
    }
    __syncthreads();

    if (threadIdx.x == 0) {
        // top-2 with first-index tie-break (matches jax top_k)
        int i0 = 0; float v0 = slog[0];
        #pragma unroll
        for (int e = 1; e < NE; e++) if (slog[e] > v0) { v0 = slog[e]; i0 = e; }
        int i1 = -1; float v1 = -INFINITY;
        #pragma unroll
        for (int e = 0; e < NE; e++) {
            if (e == i0) continue;
            if (slog[e] > v1) { v1 = slog[e]; i1 = e; }
        }
        // softmax over (v0 >= v1)
        float e1 = expf(v1 - v0);
        float inv = 1.f / (1.f + e1);
        g_expert_of_tok[t * 2 + 0] = i0; g_gate_of_tok[t * 2 + 0] = inv;
        g_expert_of_tok[t * 2 + 1] = i1; g_gate_of_tok[t * 2 + 1] = e1 * inv;
        atomicAdd(&g_counts[i0], 1);
        atomicAdd(&g_counts[i1], 1);
    }
}

// ---------------- stage 2: prefix offsets -----------------------------------
__global__ void offsets_kernel() {
    int acc = 0;
    #pragma unroll
    for (int e = 0; e < NE; e++) { g_offsets[e] = acc; acc += g_counts[e]; }
    g_offsets[NE] = acc;
}

// ---------------- stage 3: deterministic stable compaction ------------------
__global__ void build_kernel() {
    const int e = blockIdx.x;
    __shared__ int warp_sums[8];
    int base = g_offsets[e];
    const int lane = threadIdx.x & 31, w = threadIdx.x >> 5;

    for (int t0 = 0; t0 < NTOK; t0 += 256) {
        const int t = t0 + threadIdx.x;
        int k = -1;
        if (g_expert_of_tok[t * 2 + 0] == e) k = 0;
        else if (g_expert_of_tok[t * 2 + 1] == e) k = 1;
        const int flag = (k >= 0) ? 1 : 0;

        const unsigned bal = __ballot_sync(0xffffffffu, flag);
        const int pre = __popc(bal & ((1u << lane) - 1u));
        if (lane == 0) warp_sums[w] = __popc(bal);
        __syncthreads();
        int woff = 0, total = 0;
        #pragma unroll
        for (int i = 0; i < 8; i++) {
            if (i < w) woff += warp_sums[i];
            total += warp_sums[i];
        }
        if (flag) {
            const int slot = base + woff + pre;
            g_tok_of_slot[slot] = t;
            g_slot_of_tok[t * 2 + k] = slot;
        }
        base += total;
        __syncthreads();
    }
}

// ---------------- stage 4/5: routed tf32 GEMM -------------------------------
// FIRST=true : C = gelu(x[gather] @ W1[e] + b1[e])  -> g_h   (K=HD, N=FD)
// FIRST=false: C = g_h[contig] @ W2[e]              -> g_y   (K=FD, N=HD)
template <bool FIRST>
__global__ __launch_bounds__(256) void moe_gemm(const float* __restrict__ Xin,
                                                const float* __restrict__ Wmat,
                                                const float* __restrict__ bias) {
    constexpr int KDIM = FIRST ? HD : FD;
    constexpr int NDIM = FIRST ? FD : HD;

    const int e  = blockIdx.z;
    const int ne = g_counts[e];
    const int m0 = blockIdx.y * BM;
    if (m0 >= ne) return;
    const int n0  = blockIdx.x * BN;
    const int off = g_offsets[e];

    const float* Abase = FIRST ? Xin : g_h;
    float*       Cbase = FIRST ? g_h : g_y;
    const float* Wb    = Wmat + (size_t)e * KDIM * NDIM;

    __shared__ float As[2][BM][BK + PADA];
    __shared__ float Bs[2][BK][BN + PADB];
    __shared__ float bias_s[BN];

    const int tid = threadIdx.x;
    if (FIRST) {
        if (tid < BN / 4)
            ((float4*)bias_s)[tid] = ((const float4*)(bias + (size_t)e * NDIM + n0))[tid];
    }

    // A tile load mapping: 128 rows x 4 float4 per row; each thread: 2 rows
    const int ar0 = tid >> 2;
    const int ar1 = ar0 + 64;
    const int ac4 = tid & 3;
    const int grow0 = m0 + ar0, grow1 = m0 + ar1;
    const bool av0 = grow0 < ne, av1 = grow1 < ne;
    int rid0 = 0, rid1 = 0;
    if (av0) rid0 = FIRST ? g_tok_of_slot[off + grow0] : (off + grow0);
    if (av1) rid1 = FIRST ? g_tok_of_slot[off + grow1] : (off + grow1);
    const float* ap0 = Abase + (size_t)rid0 * KDIM;   // invalid rows -> row 0 (discarded)
    const float* ap1 = Abase + (size_t)rid1 * KDIM;

    // B tile load mapping: 16 rows x 32 float4; each thread: 2 rows (k, k+8)
    const int bk0 = tid >> 5;
    const int bc4 = tid & 31;
    const float* bp0 = Wb + (size_t)bk0 * NDIM + n0 + bc4 * 4;
    const float* bp1 = bp0 + (size_t)8 * NDIM;

    // warp layout: 4 warps along M (32 rows each) x 2 warps along N (64 cols)
    const int w = tid >> 5, lane = tid & 31;
    const int wm = w & 3, wn = w >> 2;
    const int g = lane >> 2, tg = lane & 3;

    float acc[2][8][4];
    #pragma unroll
    for (int i = 0; i < 2; i++)
        #pragma unroll
        for (int j = 0; j < 8; j++)
            #pragma unroll
            for (int q = 0; q < 4; q++) acc[i][j][q] = 0.f;

    const int NKI = KDIM / BK;

    // prologue: fetch k-tile 0 and stage into buffer 0
    float4 fa0 = ((const float4*)ap0)[ac4];
    float4 fa1 = ((const float4*)ap1)[ac4];
    float4 fb0 = *(const float4*)bp0;
    float4 fb1 = *(const float4*)bp1;
    *(float4*)&As[0][ar0][ac4 * 4]     = tf32x4(fa0);
    *(float4*)&As[0][ar1][ac4 * 4]     = tf32x4(fa1);
    *(float4*)&Bs[0][bk0][bc4 * 4]     = tf32x4(fb0);
    *(float4*)&Bs[0][bk0 + 8][bc4 * 4] = tf32x4(fb1);
    __syncthreads();

    for (int kt = 0; kt < NKI; kt++) {
        const int buf = kt & 1;
        if (kt + 1 < NKI) {
            fa0 = ((const float4*)(ap0 + (size_t)(kt + 1) * BK))[ac4];
            fa1 = ((const float4*)(ap1 + (size_t)(kt + 1) * BK))[ac4];
            fb0 = *(const float4*)(bp0 + (size_t)(kt + 1) * BK * NDIM);
            fb1 = *(const float4*)(bp1 + (size_t)(kt + 1) * BK * NDIM);
        }
        #pragma unroll
        for (int ks = 0; ks < 2; ks++) {
            const int kb = ks * 8 + tg;
            unsigned af[2][4];
            #pragma unroll
            for (int mi = 0; mi < 2; mi++) {
                const int mr = wm * 32 + mi * 16 + g;
                af[mi][0] = __float_as_uint(As[buf][mr][kb]);
                af[mi][1] = __float_as_uint(As[buf][mr + 8][kb]);
                af[mi][2] = __float_as_uint(As[buf][mr][kb + 4]);
                af[mi][3] = __float_as_uint(As[buf][mr + 8][kb + 4]);
            }
            unsigned bfr[8][2];
            #pragma unroll
            for (int ni = 0; ni < 8; ni++) {
                const int nc = wn * 64 + ni * 8 + g;
                bfr[ni][0] = __float_as_uint(Bs[buf][kb][nc]);
                bfr[ni][1] = __float_as_uint(Bs[buf][kb + 4][nc]);
            }
            #pragma unroll
            for (int mi = 0; mi < 2; mi++)
                #pragma unroll
                for (int ni = 0; ni < 8; ni++)
                    mma8(acc[mi][ni], af[mi][0], af[mi][1], af[mi][2], af[mi][3],
                         bfr[ni][0], bfr[ni][1]);
        }
        if (kt + 1 < NKI) {
            const int nb = buf ^ 1;
            *(float4*)&As[nb][ar0][ac4 * 4]     = tf32x4(fa0);
            *(float4*)&As[nb][ar1][ac4 * 4]     = tf32x4(fa1);
            *(float4*)&Bs[nb][bk0][bc4 * 4]     = tf32x4(fb0);
            *(float4*)&Bs[nb][bk0 + 8][bc4 * 4] = tf32x4(fb1);
            __syncthreads();
        }
    }

    // epilogue
    #pragma unroll
    for (int mi = 0; mi < 2; mi++) {
        #pragma unroll
        for (int half = 0; half < 2; half++) {
            const int mloc = wm * 32 + mi * 16 + half * 8 + g;
            const int grow = m0 + mloc;
            if (grow < ne) {
                float* cp = Cbase + (size_t)(off + grow) * NDIM + n0;
                #pragma unroll
                for (int ni = 0; ni < 8; ni++) {
                    const int nc = wn * 64 + ni * 8 + tg * 2;
                    float c0 = acc[mi][ni][half * 2 + 0];
                    float c1 = acc[mi][ni][half * 2 + 1];
                    if (FIRST) {
                        c0 = gelu_exact(c0 + bias_s[nc]);
                        c1 = gelu_exact(c1 + bias_s[nc + 1]);
                    }
                    *(float2*)(cp + nc) = make_float2(c0, c1);
                }
            }
        }
    }
}

// ---------------- stage 6: gated combine ------------------------------------
__global__ void combine_kernel(const float* __restrict__ b2,
                               float* __restrict__ out) {
    const int t  = blockIdx.x;
    const int e0 = g_expert_of_tok[t * 2 + 0], e1 = g_expert_of_tok[t * 2 + 1];
    const float gg0 = g_gate_of_tok[t * 2 + 0], gg1 = g_gate_of_tok[t * 2 + 1];
    const int s0 = g_slot_of_tok[t * 2 + 0], s1 = g_slot_of_tok[t * 2 + 1];

    const float4* y0  = (const float4*)(g_y + (size_t)s0 * HD);
    const float4* y1  = (const float4*)(g_y + (size_t)s1 * HD);
    const float4* bb0 = (const float4*)(b2 + (size_t)e0 * HD);
    const float4* bb1 = (const float4*)(b2 + (size_t)e1 * HD);
    float4* o = (float4*)(out + (size_t)t * HD);

    for (int i = threadIdx.x; i < HD / 4; i += blockDim.x) {
        const float4 a = y0[i], b = y1[i], c = bb0[i], d = bb1[i];
        float4 r;
        r.x = gg0 * (a.x + c.x) + gg1 * (b.x + d.x);
        r.y = gg0 * (a.y + c.y) + gg1 * (b.y + d.y);
        r.z = gg0 * (a.z + c.z) + gg1 * (b.z + d.z);
        r.w = gg0 * (a.w + c.w) + gg1 * (b.w + d.w);
        o[i] = r;
    }
}

// ---------------- launch -----------------------------------------------------
extern "C" void kernel_launch(void* const* d_in, const int* in_sizes, int n_in,
                              void* d_out, int out_size) {
    const float* x  = (const float*)d_in[0];
    const float* Wr = (const float*)d_in[1];
    const float* W1 = (const float*)d_in[2];
    const float* b1 = (const float*)d_in[3];
    const float* W2 = (const float*)d_in[4];
    const float* b2 = (const float*)d_in[5];
    float* out = (float*)d_out;

    init_kernel<<<1, 32>>>();
    router_kernel<<<NTOK, 256>>>(x, Wr);
    offsets_kernel<<<1, 1>>>();
    build_kernel<<<NE, 256>>>();
    moe_gemm<true><<<dim3(FD / BN, NTOK / BM, NE), 256>>>(x, W1, b1);
    moe_gemm<false><<<dim3(HD / BN, NTOK / BM, NE), 256>>>(nullptr, W2, nullptr);
    combine_kernel<<<NTOK, 256>>>(b2, out);
}

// round 2
// speedup vs baseline: 1.0000x; 1.0000x over previous
#include <cuda_runtime.h>
#include <math.h>

// Problem constants (fixed shapes from the reference)
#define NTOK 4096     // B*S = 2*2048
#define HD   1024     // hidden
#define NE   8        // experts
#define FD   4096     // ffn dim
#define NSLOT (NTOK * 2)   // top-2 -> exactly 8192 assignments

// GEMM tiling
#define BM 128
#define BN 128
#define BK 16
#define PADA 4        // As row pad: ld = BK+4 = 20 floats (conflict-free frag reads)
#define PADB 8        // Bs row pad: ld = BN+8 = 136 floats

// ---------------- scratch (device globals; no allocation in kernel_launch) ---
__device__ float g_h[(size_t)NSLOT * FD];   // gelu(x@W1+b1) per assignment  (128MB)
__device__ float g_y[(size_t)NSLOT * HD];   // h@W2 per assignment           (32MB)
__device__ int   g_tok_of_slot[NSLOT];
__device__ int   g_slot_of_tok[NSLOT];      // [token*2 + k]
__device__ int   g_expert_of_tok[NSLOT];    // [token*2 + k]
__device__ float g_gate_of_tok[NSLOT];      // [token*2 + k]
__device__ int   g_counts[NE];
__device__ int   g_offsets[NE + 1];

// ---------------- helpers ---------------------------------------------------
__device__ __forceinline__ float tf32r(float f) {
    unsigned u;
    asm("cvt.rna.tf32.f32 %0, %1;" : "=r"(u) : "f"(f));
    return __uint_as_float(u);
}

__device__ __forceinline__ float4 tf32x4(float4 v) {
    return make_float4(tf32r(v.x), tf32r(v.y), tf32r(v.z), tf32r(v.w));
}

__device__ __forceinline__ void mma8(float c[4],
                                     unsigned a0, unsigned a1, unsigned a2, unsigned a3,
                                     unsigned b0, unsigned b1) {
    asm volatile(
        "mma.sync.aligned.m16n8k8.row.col.f32.tf32.tf32.f32 "
        "{%0,%1,%2,%3}, {%4,%5,%6,%7}, {%8,%9}, {%0,%1,%2,%3};\n"
        : "+f"(c[0]), "+f"(c[1]), "+f"(c[2]), "+f"(c[3])
        : "r"(a0), "r"(a1), "r"(a2), "r"(a3), "r"(b0), "r"(b1));
}

__device__ __forceinline__ float gelu_exact(float x) {
    return 0.5f * x * (1.0f + erff(x * 0.70710678118654752440f));
}

// ---------------- stage 0: zero counts --------------------------------------
__global__ void init_kernel() {
    if (threadIdx.x < NE) g_counts[threadIdx.x] = 0;
}

// ---------------- stage 1: router (logits, top-2, softmax) ------------------
__global__ void router_kernel(const float* __restrict__ x,
                              const float* __restrict__ Wr) {
    const int t = blockIdx.x;
    __shared__ float sx[HD];
    __shared__ float slog[NE];

    const float* xr = x + (size_t)t * HD;
    for (int i = threadIdx.x; i < HD; i += blockDim.x) sx[i] = xr[i];
    __syncthreads();

    const int w = threadIdx.x >> 5, lane = threadIdx.x & 31;
    if (w < NE) {
        const float* wr = Wr + (size_t)w * HD;
        float s = 0.f;
        for (int i = lane; i < HD; i += 32) s += sx[i] * wr[i];
        #pragma unroll
        for (int o = 16; o > 0; o >>= 1) s += __shfl_xor_sync(0xffffffffu, s, o);
        if (lane == 0) slog[w] = s;
    }
    __syncthreads();

    if (threadIdx.x == 0) {
        // top-2 with first-index tie-break (matches jax top_k)
        int i0 = 0; float v0 = slog[0];
        #pragma unroll
        for (int e = 1; e < NE; e++) if (slog[e] > v0) { v0 = slog[e]; i0 = e; }
        int i1 = -1; float v1 = -INFINITY;
        #pragma unroll
        for (int e = 0; e < NE; e++) {
            if (e == i0) continue;
            if (slog[e] > v1) { v1 = slog[e]; i1 = e; }
        }
        // softmax over (v0 >= v1)
        float e1 = expf(v1 - v0);
        float inv = 1.f / (1.f + e1);
        g_expert_of_tok[t * 2 + 0] = i0; g_gate_of_tok[t * 2 + 0] = inv;
        g_expert_of_tok[t * 2 + 1] = i1; g_gate_of_tok[t * 2 + 1] = e1 * inv;
        atomicAdd(&g_counts[i0], 1);
        atomicAdd(&g_counts[i1], 1);
    }
}

// ---------------- stage 2: prefix offsets -----------------------------------
__global__ void offsets_kernel() {
    int acc = 0;
    #pragma unroll
    for (int e = 0; e < NE; e++) { g_offsets[e] = acc; acc += g_counts[e]; }
    g_offsets[NE] = acc;
}

// ---------------- stage 3: deterministic stable compaction ------------------
__global__ void build_kernel() {
    const int e = blockIdx.x;
    __shared__ int warp_sums[8];
    int base = g_offsets[e];
    const int lane = threadIdx.x & 31, w = threadIdx.x >> 5;

    for (int t0 = 0; t0 < NTOK; t0 += 256) {
        const int t = t0 + threadIdx.x;
        int k = -1;
        if (g_expert_of_tok[t * 2 + 0] == e) k = 0;
        else if (g_expert_of_tok[t * 2 + 1] == e) k = 1;
        const int flag = (k >= 0) ? 1 : 0;

        const unsigned bal = __ballot_sync(0xffffffffu, flag);
        const int pre = __popc(bal & ((1u << lane) - 1u));
        if (lane == 0) warp_sums[w] = __popc(bal);
        __syncthreads();
        int woff = 0, total = 0;
        #pragma unroll
        for (int i = 0; i < 8; i++) {
            if (i < w) woff += warp_sums[i];
            total += warp_sums[i];
        }
        if (flag) {
            const int slot = base + woff + pre;
            g_tok_of_slot[slot] = t;
            g_slot_of_tok[t * 2 + k] = slot;
        }
        base += total;
        __syncthreads();
    }
}

// ---------------- stage 4/5: routed tf32 GEMM -------------------------------
// FIRST=true : C = gelu(x[gather] @ W1[e] + b1[e])  -> g_h   (K=HD, N=FD)
// FIRST=false: C = g_h[contig] @ W2[e]              -> g_y   (K=FD, N=HD)
template <bool FIRST>
__global__ __launch_bounds__(256) void moe_gemm(const float* __restrict__ Xin,
                                                const float* __restrict__ Wmat,
                                                const float* __restrict__ bias) {
    constexpr int KDIM = FIRST ? HD : FD;
    constexpr int NDIM = FIRST ? FD : HD;

    const int e  = blockIdx.z;
    const int ne = g_counts[e];
    const int m0 = blockIdx.y * BM;
    if (m0 >= ne) return;
    const int n0  = blockIdx.x * BN;
    const int off = g_offsets[e];

    const float* Abase = FIRST ? Xin : g_h;
    float*       Cbase = FIRST ? g_h : g_y;
    const float* Wb    = Wmat + (size_t)e * KDIM * NDIM;

    __shared__ float As[2][BM][BK + PADA];
    __shared__ float Bs[2][BK][BN + PADB];
    __shared__ float bias_s[BN];

    const int tid = threadIdx.x;
    if (FIRST) {
        if (tid < BN / 4)
            ((float4*)bias_s)[tid] = ((const float4*)(bias + (size_t)e * NDIM + n0))[tid];
    }

    // A tile load mapping: 128 rows x 4 float4 per row; each thread: 2 rows
    const int ar0 = tid >> 2;
    const int ar1 = ar0 + 64;
    const int ac4 = tid & 3;
    const int grow0 = m0 + ar0, grow1 = m0 + ar1;
    const bool av0 = grow0 < ne, av1 = grow1 < ne;
    int rid0 = 0, rid1 = 0;
    if (av0) rid0 = FIRST ? g_tok_of_slot[off + grow0] : (off + grow0);
    if (av1) rid1 = FIRST ? g_tok_of_slot[off + grow1] : (off + grow1);
    const float* ap0 = Abase + (size_t)rid0 * KDIM;   // invalid rows -> row 0 (discarded)
    const float* ap1 = Abase + (size_t)rid1 * KDIM;

    // B tile load mapping: 16 rows x 32 float4; each thread: 2 rows (k, k+8)
    const int bk0 = tid >> 5;
    const int bc4 = tid & 31;
    const float* bp0 = Wb + (size_t)bk0 * NDIM + n0 + bc4 * 4;
    const float* bp1 = bp0 + (size_t)8 * NDIM;

    // warp layout: 4 warps along M (32 rows each) x 2 warps along N (64 cols)
    const int w = tid >> 5, lane = tid & 31;
    const int wm = w & 3, wn = w >> 2;
    const int g = lane >> 2, tg = lane & 3;

    float acc[2][8][4];
    #pragma unroll
    for (int i = 0; i < 2; i++)
        #pragma unroll
        for (int j = 0; j < 8; j++)
            #pragma unroll
            for (int q = 0; q < 4; q++) acc[i][j][q] = 0.f;

    const int NKI = KDIM / BK;

    // prologue: fetch k-tile 0 and stage into buffer 0
    float4 fa0 = ((const float4*)ap0)[ac4];
    float4 fa1 = ((const float4*)ap1)[ac4];
    float4 fb0 = *(const float4*)bp0;
    float4 fb1 = *(const float4*)bp1;
    *(float4*)&As[0][ar0][ac4 * 4]     = tf32x4(fa0);
    *(float4*)&As[0][ar1][ac4 * 4]     = tf32x4(fa1);
    *(float4*)&Bs[0][bk0][bc4 * 4]     = tf32x4(fb0);
    *(float4*)&Bs[0][bk0 + 8][bc4 * 4] = tf32x4(fb1);
    __syncthreads();

    for (int kt = 0; kt < NKI; kt++) {
        const int buf = kt & 1;
        if (kt + 1 < NKI) {
            fa0 = ((const float4*)(ap0 + (size_t)(kt + 1) * BK))[ac4];
            fa1 = ((const float4*)(ap1 + (size_t)(kt + 1) * BK))[ac4];
            fb0 = *(const float4*)(bp0 + (size_t)(kt + 1) * BK * NDIM);
            fb1 = *(const float4*)(bp1 + (size_t)(kt + 1) * BK * NDIM);
        }
        #pragma unroll
        for (int ks = 0; ks < 2; ks++) {
            const int kb = ks * 8 + tg;
            unsigned af[2][4];
            #pragma unroll
            for (int mi = 0; mi < 2; mi++) {
                const int mr = wm * 32 + mi * 16 + g;
                af[mi][0] = __float_as_uint(As[buf][mr][kb]);
                af[mi][1] = __float_as_uint(As[buf][mr + 8][kb]);
                af[mi][2] = __float_as_uint(As[buf][mr][kb + 4]);
                af[mi][3] = __float_as_uint(As[buf][mr + 8][kb + 4]);
            }
            unsigned bfr[8][2];
            #pragma unroll
            for (int ni = 0; ni < 8; ni++) {
                const int nc = wn * 64 + ni * 8 + g;
                bfr[ni][0] = __float_as_uint(Bs[buf][kb][nc]);
                bfr[ni][1] = __float_as_uint(Bs[buf][kb + 4][nc]);
            }
            #pragma unroll
            for (int mi = 0; mi < 2; mi++)
                #pragma unroll
                for (int ni = 0; ni < 8; ni++)
                    mma8(acc[mi][ni], af[mi][0], af[mi][1], af[mi][2], af[mi][3],
                         bfr[ni][0], bfr[ni][1]);
        }
        if (kt + 1 < NKI) {
            const int nb = buf ^ 1;
            *(float4*)&As[nb][ar0][ac4 * 4]     = tf32x4(fa0);
            *(float4*)&As[nb][ar1][ac4 * 4]     = tf32x4(fa1);
            *(float4*)&Bs[nb][bk0][bc4 * 4]     = tf32x4(fb0);
            *(float4*)&Bs[nb][bk0 + 8][bc4 * 4] = tf32x4(fb1);
            __syncthreads();
        }
    }

    // epilogue
    #pragma unroll
    for (int mi = 0; mi < 2; mi++) {
        #pragma unroll
        for (int half = 0; half < 2; half++) {
            const int mloc = wm * 32 + mi * 16 + half * 8 + g;
            const int grow = m0 + mloc;
            if (grow < ne) {
                float* cp = Cbase + (size_t)(off + grow) * NDIM + n0;
                #pragma unroll
                for (int ni = 0; ni < 8; ni++) {
                    const int nc = wn * 64 + ni * 8 + tg * 2;
                    float c0 = acc[mi][ni][half * 2 + 0];
                    float c1 = acc[mi][ni][half * 2 + 1];
                    if (FIRST) {
                        c0 = gelu_exact(c0 + bias_s[nc]);
                        c1 = gelu_exact(c1 + bias_s[nc + 1]);
                    }
                    *(float2*)(cp + nc) = make_float2(c0, c1);
                }
            }
        }
    }
}

// ---------------- stage 6: gated combine ------------------------------------
__global__ void combine_kernel(const float* __restrict__ b2,
                               float* __restrict__ out) {
    const int t  = blockIdx.x;
    const int e0 = g_expert_of_tok[t * 2 + 0], e1 = g_expert_of_tok[t * 2 + 1];
    const float gg0 = g_gate_of_tok[t * 2 + 0], gg1 = g_gate_of_tok[t * 2 + 1];
    const int s0 = g_slot_of_tok[t * 2 + 0], s1 = g_slot_of_tok[t * 2 + 1];

    const float4* y0  = (const float4*)(g_y + (size_t)s0 * HD);
    const float4* y1  = (const float4*)(g_y + (size_t)s1 * HD);
    const float4* bb0 = (const float4*)(b2 + (size_t)e0 * HD);
    const float4* bb1 = (const float4*)(b2 + (size_t)e1 * HD);
    float4* o = (float4*)(out + (size_t)t * HD);

    for (int i = threadIdx.x; i < HD / 4; i += blockDim.x) {
        const float4 a = y0[i], b = y1[i], c = bb0[i], d = bb1[i];
        float4 r;
        r.x = gg0 * (a.x + c.x) + gg1 * (b.x + d.x);
        r.y = gg0 * (a.y + c.y) + gg1 * (b.y + d.y);
        r.z = gg0 * (a.z + c.z) + gg1 * (b.z + d.z);
        r.w = gg0 * (a.w + c.w) + gg1 * (b.w + d.w);
        o[i] = r;
    }
}

// ---------------- launch -----------------------------------------------------
extern "C" void kernel_launch(void* const* d_in, const int* in_sizes, int n_in,
                              void* d_out, int out_size) {
    const float* x  = (const float*)d_in[0];
    const float* Wr = (const float*)d_in[1];
    const float* W1 = (const float*)d_in[2];
    const float* b1 = (const float*)d_in[3];
    const float* W2 = (const float*)d_in[4];
    const float* b2 = (const float*)d_in[5];
    float* out = (float*)d_out;

    init_kernel<<<1, 32>>>();
    router_kernel<<<NTOK, 256>>>(x, Wr);
    offsets_kernel<<<1, 1>>>();
    build_kernel<<<NE, 256>>>();
    moe_gemm<true><<<dim3(FD / BN, NTOK / BM, NE), 256>>>(x, W1, b1);
    moe_gemm<false><<<dim3(HD / BN, NTOK / BM, NE), 256>>>(nullptr, W2, nullptr);
    combine_kernel<<<NTOK, 256>>>(b2, out);
}

// round 4
// speedup vs baseline: 1.7451x; 1.7450x over previous
#include <cuda_runtime.h>
#include <cuda_fp16.h>
#include <math.h>
#include <stdint.h>

// ---------------- problem constants -----------------------------------------
#define NTOK 4096
#define HD   1024
#define NE   8
#define FD   4096
#define NSLOT (NTOK * 2)

// ---------------- GEMM tiling (fp16 mma.sync + ldmatrix) ---------------------
#define BM 128
#define BN 256
#define BK 32

// dynamic smem layout (bytes)
#define SM_A    0          // 2 bufs x 128x32 fp16  = 2 x 8192
#define SM_B    16384      // 2 bufs x 32x256 fp16  = 2 x 16384
#define SM_BIAS 49152      // 256 fp32
#define SMEM_BYTES 50176

// ---------------- scratch (device globals; no allocations) -------------------
__device__ __half g_h[(size_t)NSLOT * FD];   // fp16 gelu(xW1+b1) (64MB)
__device__ float  g_y[(size_t)NSLOT * HD];   // fp32 hW2          (32MB)
__device__ int    g_tok_of_slot[NSLOT];
__device__ int    g_slot_of_tok[NSLOT];
__device__ int    g_expert_of_tok[NSLOT];
__device__ float  g_gate_of_tok[NSLOT];
__device__ int    g_counts[NE];
__device__ int    g_offsets[NE + 1];

// ---------------- helpers ----------------------------------------------------
__device__ __forceinline__ uint32_t smem_u32(const void* p) {
    uint32_t a;
    asm("{ .reg .u64 t; cvta.to.shared.u64 t, %1; cvt.u32.u64 %0, t; }" : "=r"(a) : "l"(p));
    return a;
}

__device__ __forceinline__ uint32_t f22h(float lo, float hi) {
    __half2 h = __floats2half2_rn(lo, hi);   // x = lo (low address)
    return *(uint32_t*)&h;
}

__device__ __forceinline__ void ldsm4(uint32_t r[4], uint32_t addr) {
    asm volatile("ldmatrix.sync.aligned.m8n8.x4.shared.b16 {%0,%1,%2,%3}, [%4];"
                 : "=r"(r[0]), "=r"(r[1]), "=r"(r[2]), "=r"(r[3]) : "r"(addr));
}
__device__ __forceinline__ void ldsm4t(uint32_t r[4], uint32_t addr) {
    asm volatile("ldmatrix.sync.aligned.m8n8.x4.trans.shared.b16 {%0,%1,%2,%3}, [%4];"
                 : "=r"(r[0]), "=r"(r[1]), "=r"(r[2]), "=r"(r[3]) : "r"(addr));
}

__device__ __forceinline__ void mma16816(float c[4], const uint32_t a[4],
                                         uint32_t b0, uint32_t b1) {
    asm volatile(
        "mma.sync.aligned.m16n8k16.row.col.f32.f16.f16.f32 "
        "{%0,%1,%2,%3}, {%4,%5,%6,%7}, {%8,%9}, {%0,%1,%2,%3};\n"
        : "+f"(c[0]), "+f"(c[1]), "+f"(c[2]), "+f"(c[3])
        : "r"(a[0]), "r"(a[1]), "r"(a[2]), "r"(a[3]), "r"(b0), "r"(b1));
}

__device__ __forceinline__ float gelu_exact(float x) {
    return 0.5f * x * (1.0f + erff(x * 0.70710678118654752440f));
}

// ---------------- stage 0: zero counts ---------------------------------------
__global__ void init_kernel() {
    if (threadIdx.x < NE) g_counts[threadIdx.x] = 0;
}

// ---------------- stage 1: router --------------------------------------------
__global__ void router_kernel(const float* __restrict__ x,
                              const float* __restrict__ Wr) {
    const int t = blockIdx.x;
    __shared__ float sx[HD];
    __shared__ float slog[NE];

    const float* xr = x + (size_t)t * HD;
    for (int i = threadIdx.x; i < HD; i += blockDim.x) sx[i] = xr[i];
    __syncthreads();

    const int w = threadIdx.x >> 5, lane = threadIdx.x & 31;
    if (w < NE) {
        const float* wr = Wr + (size_t)w * HD;
        float s = 0.f;
        for (int i = lane; i < HD; i += 32) s += sx[i] * wr[i];
        #pragma unroll
        for (int o = 16; o > 0; o >>= 1) s += __shfl_xor_sync(0xffffffffu, s, o);
        if (lane == 0) slog[w] = s;
    }
    __syncthreads();

    if (threadIdx.x == 0) {
        int i0 = 0; float v0 = slog[0];
        #pragma unroll
        for (int e = 1; e < NE; e++) if (slog[e] > v0) { v0 = slog[e]; i0 = e; }
        int i1 = -1; float v1 = -INFINITY;
        #pragma unroll
        for (int e = 0; e < NE; e++) {
            if (e == i0) continue;
            if (slog[e] > v1) { v1 = slog[e]; i1 = e; }
        }
        float e1 = expf(v1 - v0);
        float inv = 1.f / (1.f + e1);
        g_expert_of_tok[t * 2 + 0] = i0; g_gate_of_tok[t * 2 + 0] = inv;
        g_expert_of_tok[t * 2 + 1] = i1; g_gate_of_tok[t * 2 + 1] = e1 * inv;
        atomicAdd(&g_counts[i0], 1);
        atomicAdd(&g_counts[i1], 1);
    }
}

// ---------------- stage 2: prefix offsets ------------------------------------
__global__ void offsets_kernel() {
    int acc = 0;
    #pragma unroll
    for (int e = 0; e < NE; e++) { g_offsets[e] = acc; acc += g_counts[e]; }
    g_offsets[NE] = acc;
}

// ---------------- stage 3: deterministic stable compaction -------------------
__global__ void build_kernel() {
    const int e = blockIdx.x;
    __shared__ int warp_sums[32];
    int base = g_offsets[e];
    const int lane = threadIdx.x & 31, w = threadIdx.x >> 5;

    for (int t0 = 0; t0 < NTOK; t0 += 1024) {
        const int t = t0 + threadIdx.x;
        int k = -1;
        if (g_expert_of_tok[t * 2 + 0] == e) k = 0;
        else if (g_expert_of_tok[t * 2 + 1] == e) k = 1;
        const int flag = (k >= 0) ? 1 : 0;

        const unsigned bal = __ballot_sync(0xffffffffu, flag);
        const int pre = __popc(bal & ((1u << lane) - 1u));
        if (lane == 0) warp_sums[w] = __popc(bal);
        __syncthreads();
        int woff = 0, total = 0;
        #pragma unroll
        for (int i = 0; i < 32; i++) {
            if (i < w) woff += warp_sums[i];
            total += warp_sums[i];
        }
        if (flag) {
            const int slot = base + woff + pre;
            g_tok_of_slot[slot] = t;
            g_slot_of_tok[t * 2 + k] = slot;
        }
        base += total;
        __syncthreads();
    }
}

// ---------------- stage 4/5: routed fp16 mma GEMM (128x256x32) ---------------
// FIRST=true : g_h(fp16) = gelu(x[gather] @ W1[e] + b1[e])   K=HD,  N=FD
// FIRST=false: g_y(fp32) = g_h[contig] @ W2[e]               K=FD,  N=HD
template <bool FIRST>
__global__ __launch_bounds__(256) void moe_mma(const float* __restrict__ Xin,
                                               const float* __restrict__ Wmat,
                                               const float* __restrict__ bias) {
    constexpr int KDIM = FIRST ? HD : FD;
    constexpr int NDIM = FIRST ? FD : HD;
    constexpr int NKT  = KDIM / BK;

    const int e  = blockIdx.z;
    const int ne = g_counts[e];
    const int m0 = blockIdx.y * BM;
    if (m0 >= ne) return;
    const int n0  = blockIdx.x * BN;
    const int off = g_offsets[e];

    extern __shared__ char smem[];
    const uint32_t sb = smem_u32(smem);
    const int tid = threadIdx.x;

    if (FIRST && tid < 64)
        ((float4*)(smem + SM_BIAS))[tid] =
            ((const float4*)(bias + (size_t)e * NDIM + n0))[tid];

    const float*  Wb = Wmat + (size_t)e * KDIM * NDIM;

    // ---- staging maps ----
    // A: thread -> row r = tid>>1, granule pair hs = tid&1 (granule = 8 halves)
    const int r  = tid >> 1, hs = tid & 1;
    int ga = m0 + r; if (ga > ne - 1) ga = ne - 1;
    const int rowid = FIRST ? g_tok_of_slot[off + ga] : (off + ga);
    const float*  aF = FIRST ? (Xin + (size_t)rowid * KDIM + hs * 16) : nullptr;
    const __half* aH = FIRST ? nullptr : (g_h + (size_t)rowid * KDIM + hs * 16);
    const int g0 = hs * 2;
    const uint32_t asts0 = (uint32_t)(r * 64 + (((g0 + 0) ^ ((r >> 1) & 3)) * 16));
    const uint32_t asts1 = (uint32_t)(r * 64 + (((g0 + 1) ^ ((r >> 1) & 3)) * 16));

    // B: thread -> k-row kk = tid>>3, lane8 = tid&7, granules g = lane8 + 8j
    const int kk = tid >> 3, lane8 = tid & 7;
    const float* bF = Wb + (size_t)kk * NDIM + n0 + lane8 * 8;
    uint32_t bsts[4];
    #pragma unroll
    for (int j = 0; j < 4; j++)
        bsts[j] = (uint32_t)(kk * 512 + (((lane8 + 8 * j) ^ (kk & 7)) * 16));

    // ---- fragment (ldmatrix) address maps: warp grid 2(M) x 4(N) ----
    const int w = tid >> 5, lane = tid & 31;
    const int wm = w & 1, wn = w >> 1;
    const int l16 = lane & 15, lh = lane >> 4;
    uint32_t ao[2][4], bo[2][4];
    #pragma unroll
    for (int ks = 0; ks < 2; ks++) {
        #pragma unroll
        for (int mi = 0; mi < 4; mi++) {
            const int row = wm * 64 + mi * 16 + l16;
            const int gr  = ks * 2 + lh;
            ao[ks][mi] = (uint32_t)(row * 64 + ((gr ^ ((row >> 1) & 3)) * 16));
        }
        #pragma unroll
        for (int np = 0; np < 4; np++) {
            const int kr = ks * 16 + l16;
            const int ng = wn * 8 + np * 2 + lh;
            bo[ks][np] = (uint32_t)(kr * 512 + ((ng ^ (kr & 7)) * 16));
        }
    }

    float acc[4][8][4];
    #pragma unroll
    for (int mi = 0; mi < 4; mi++)
        #pragma unroll
        for (int ni = 0; ni < 8; ni++)
            #pragma unroll
            for (int q = 0; q < 4; q++) acc[mi][ni][q] = 0.f;

    // ---- prefetch registers ----
    float4 paf[4]; uint4 pah[2]; float4 pb[8];

    auto load_regs = [&](int kt) {
        if (FIRST) {
            const float4* ap = (const float4*)(aF + (size_t)kt * BK);
            #pragma unroll
            for (int j = 0; j < 4; j++) paf[j] = ap[j];
        } else {
            const uint4* ap = (const uint4*)(aH + (size_t)kt * BK);
            pah[0] = ap[0]; pah[1] = ap[1];
        }
        const float4* bp = (const float4*)(bF + (size_t)kt * BK * NDIM);
        #pragma unroll
        for (int j = 0; j < 4; j++) { pb[2 * j] = bp[16 * j]; pb[2 * j + 1] = bp[16 * j + 1]; }
    };

    auto store_smem = [&](int buf) {
        char* sa = smem + SM_A + buf * 8192;
        char* sbm = smem + SM_B + buf * 16384;
        if (FIRST) {
            uint4 u0 = make_uint4(f22h(paf[0].x, paf[0].y), f22h(paf[0].z, paf[0].w),
                                  f22h(paf[1].x, paf[1].y), f22h(paf[1].z, paf[1].w));
            uint4 u1 = make_uint4(f22h(paf[2].x, paf[2].y), f22h(paf[2].z, paf[2].w),
                                  f22h(paf[3].x, paf[3].y), f22h(paf[3].z, paf[3].w));
            *(uint4*)(sa + asts0) = u0;
            *(uint4*)(sa + asts1) = u1;
        } else {
            *(uint4*)(sa + asts0) = pah[0];
            *(uint4*)(sa + asts1) = pah[1];
        }
        #pragma unroll
        for (int j = 0; j < 4; j++) {
            uint4 ub = make_uint4(f22h(pb[2*j].x, pb[2*j].y),   f22h(pb[2*j].z, pb[2*j].w),
                                  f22h(pb[2*j+1].x, pb[2*j+1].y), f22h(pb[2*j+1].z, pb[2*j+1].w));
            *(uint4*)(sbm + bsts[j]) = ub;
        }
    };

    // ---- prologue ----
    load_regs(0);
    store_smem(0);
    __syncthreads();

    // ---- mainloop ----
    #pragma unroll 1
    for (int kt = 0; kt < NKT; kt++) {
        const int buf = kt & 1;
        const bool more = (kt + 1) < NKT;
        if (more) load_regs(kt + 1);

        const uint32_t sA = sb + SM_A + buf * 8192;
        const uint32_t sB = sb + SM_B + buf * 16384;
        #pragma unroll
        for (int ks = 0; ks < 2; ks++) {
            uint32_t af[4][4];
            #pragma unroll
            for (int mi = 0; mi < 4; mi++) ldsm4(af[mi], sA + ao[ks][mi]);
            #pragma unroll
            for (int np = 0; np < 4; np++) {
                uint32_t bf[4];
                ldsm4t(bf, sB + bo[ks][np]);
                #pragma unroll
                for (int mi = 0; mi < 4; mi++) {
                    mma16816(acc[mi][np * 2 + 0], af[mi], bf[0], bf[1]);
                    mma16816(acc[mi][np * 2 + 1], af[mi], bf[2], bf[3]);
                }
            }
        }

        if (more) {
            store_smem(buf ^ 1);
            __syncthreads();
        }
    }

    // ---- epilogue ----
    const int rbase = wm * 64 + (lane >> 2);
    const int cbase = wn * 64 + (lane & 3) * 2;
    #pragma unroll
    for (int mi = 0; mi < 4; mi++) {
        #pragma unroll
        for (int hrow = 0; hrow < 2; hrow++) {
            const int mloc = rbase + mi * 16 + hrow * 8;
            const int grow = m0 + mloc;
            if (grow >= ne) continue;
            #pragma unroll
            for (int ni = 0; ni < 8; ni++) {
                const int cr = cbase + ni * 8;          // col within BN
                float v0 = acc[mi][ni][hrow * 2 + 0];
                float v1 = acc[mi][ni][hrow * 2 + 1];
                if (FIRST) {
                    const float2 bv = *(const float2*)(smem + SM_BIAS + cr * 4);
                    v0 = gelu_exact(v0 + bv.x);
                    v1 = gelu_exact(v1 + bv.y);
                    __half2 hv = __floats2half2_rn(v0, v1);
                    *(__half2*)(g_h + (size_t)(off + grow) * NDIM + n0 + cr) = hv;
                } else {
                    *(float2*)(g_y + (size_t)(off + grow) * NDIM + n0 + cr) =
                        make_float2(v0, v1);
                }
            }
        }
    }
}

// ---------------- stage 6: gated combine -------------------------------------
__global__ void combine_kernel(const float* __restrict__ b2,
                               float* __restrict__ out) {
    const int t  = blockIdx.x;
    const int e0 = g_expert_of_tok[t * 2 + 0], e1 = g_expert_of_tok[t * 2 + 1];
    const float gg0 = g_gate_of_tok[t * 2 + 0], gg1 = g_gate_of_tok[t * 2 + 1];
    const int s0 = g_slot_of_tok[t * 2 + 0], s1 = g_slot_of_tok[t * 2 + 1];

    const float4* y0  = (const float4*)(g_y + (size_t)s0 * HD);
    const float4* y1  = (const float4*)(g_y + (size_t)s1 * HD);
    const float4* bb0 = (const float4*)(b2 + (size_t)e0 * HD);
    const float4* bb1 = (const float4*)(b2 + (size_t)e1 * HD);
    float4* o = (float4*)(out + (size_t)t * HD);

    for (int i = threadIdx.x; i < HD / 4; i += blockDim.x) {
        const float4 a = y0[i], b = y1[i], c = bb0[i], d = bb1[i];
        float4 rr;
        rr.x = gg0 * (a.x + c.x) + gg1 * (b.x + d.x);
        rr.y = gg0 * (a.y + c.y) + gg1 * (b.y + d.y);
        rr.z = gg0 * (a.z + c.z) + gg1 * (b.z + d.z);
        rr.w = gg0 * (a.w + c.w) + gg1 * (b.w + d.w);
        o[i] = rr;
    }
}

// ---------------- launch ------------------------------------------------------
extern "C" void kernel_launch(void* const* d_in, const int* in_sizes, int n_in,
                              void* d_out, int out_size) {
    const float* x  = (const float*)d_in[0];
    const float* Wr = (const float*)d_in[1];
    const float* W1 = (const float*)d_in[2];
    const float* b1 = (const float*)d_in[3];
    const float* W2 = (const float*)d_in[4];
    const float* b2 = (const float*)d_in[5];
    float* out = (float*)d_out;

    cudaFuncSetAttribute(moe_mma<true>,  cudaFuncAttributeMaxDynamicSharedMemorySize, SMEM_BYTES);
    cudaFuncSetAttribute(moe_mma<false>, cudaFuncAttributeMaxDynamicSharedMemorySize, SMEM_BYTES);

    init_kernel<<<1, 32>>>();
    router_kernel<<<NTOK, 256>>>(x, Wr);
    offsets_kernel<<<1, 1>>>();
    build_kernel<<<NE, 1024>>>();
    moe_mma<true><<<dim3(FD / BN, NSLOT / BM, NE), 256, SMEM_BYTES>>>(x, W1, b1);
    moe_mma<false><<<dim3(HD / BN, NSLOT / BM, NE), 256, SMEM_BYTES>>>(nullptr, W2, nullptr);
    combine_kernel<<<NTOK, 256>>>(b2, out);
}

// round 5
// speedup vs baseline: 2.2255x; 1.2753x over previous
#include <cuda_runtime.h>
#include <cuda_fp16.h>
#include <math.h>
#include <stdint.h>

// ---------------- problem constants -----------------------------------------
#define NTOK 4096
#define HD   1024
#define NE   8
#define FD   4096
#define NSLOT (NTOK * 2)

// ---------------- GEMM tiling (fp16 mma.sync + ldmatrix + cp.async) ----------
#define BM 128
#define BN 256
#define BK 32
#define STAGES 4

// dynamic smem layout (bytes)
#define SM_A    0                      // STAGES x 128x32 fp16 = 4 x 8192
#define SM_B    (STAGES * 8192)        // STAGES x 32x256 fp16 = 4 x 16384
#define SM_BIAS (SM_A + STAGES * 8192 + STAGES * 16384)   // 98304
#define SMEM_BYTES (SM_BIAS + 1024)    // 99328

// ---------------- scratch (device globals; no allocations) -------------------
__device__ __align__(128) __half g_xh[(size_t)NTOK * HD];       // fp16 x (8MB)
__device__ __align__(128) __half g_w1h[(size_t)NE * HD * FD];   // fp16 W1 (64MB)
__device__ __align__(128) __half g_w2h[(size_t)NE * FD * HD];   // fp16 W2 (64MB)
__device__ __align__(128) __half g_h[(size_t)NSLOT * FD];       // fp16 act (64MB)
__device__ float  g_y[(size_t)NSLOT * HD];
__device__ int    g_tok_of_slot[NSLOT];
__device__ int    g_slot_of_tok[NSLOT];
__device__ int    g_expert_of_tok[NSLOT];
__device__ float  g_gate_of_tok[NSLOT];
__device__ int    g_counts[NE];

// ---------------- helpers ----------------------------------------------------
__device__ __forceinline__ uint32_t smem_u32(const void* p) {
    uint32_t a;
    asm("{ .reg .u64 t; cvta.to.shared.u64 t, %1; cvt.u32.u64 %0, t; }" : "=r"(a) : "l"(p));
    return a;
}

__device__ __forceinline__ void cp16(uint32_t dst, const void* src) {
    asm volatile("cp.async.cg.shared.global [%0], [%1], 16;" :: "r"(dst), "l"(src));
}
__device__ __forceinline__ void cp_commit() {
    asm volatile("cp.async.commit_group;" ::: "memory");
}
__device__ __forceinline__ void cp_wait2() {
    asm volatile("cp.async.wait_group 2;" ::: "memory");
}

__device__ __forceinline__ void ldsm4(uint32_t r[4], uint32_t addr) {
    asm volatile("ldmatrix.sync.aligned.m8n8.x4.shared.b16 {%0,%1,%2,%3}, [%4];"
                 : "=r"(r[0]), "=r"(r[1]), "=r"(r[2]), "=r"(r[3]) : "r"(addr));
}
__device__ __forceinline__ void ldsm4t(uint32_t r[4], uint32_t addr) {
    asm volatile("ldmatrix.sync.aligned.m8n8.x4.trans.shared.b16 {%0,%1,%2,%3}, [%4];"
                 : "=r"(r[0]), "=r"(r[1]), "=r"(r[2]), "=r"(r[3]) : "r"(addr));
}

__device__ __forceinline__ void mma16816(float c[4], const uint32_t a[4],
                                         uint32_t b0, uint32_t b1) {
    asm volatile(
        "mma.sync.aligned.m16n8k16.row.col.f32.f16.f16.f32 "
        "{%0,%1,%2,%3}, {%4,%5,%6,%7}, {%8,%9}, {%0,%1,%2,%3};\n"
        : "+f"(c[0]), "+f"(c[1]), "+f"(c[2]), "+f"(c[3])
        : "r"(a[0]), "r"(a[1]), "r"(a[2]), "r"(a[3]), "r"(b0), "r"(b1));
}

__device__ __forceinline__ float gelu_exact(float x) {
    return 0.5f * x * (1.0f + erff(x * 0.70710678118654752440f));
}

// ---------------- stage 1: weight fp16 pre-convert (+zero counts) ------------
__global__ void cvt_kernel(const float* __restrict__ W1,
                           const float* __restrict__ W2) {
    if (blockIdx.x == 0 && blockIdx.y == 0 && threadIdx.x < NE)
        g_counts[threadIdx.x] = 0;
    const float* src = blockIdx.y ? W2 : W1;
    __half* dst = blockIdx.y ? g_w2h : g_w1h;
    const size_t n4 = (size_t)NE * HD * FD / 4;
    const size_t stride = (size_t)gridDim.x * blockDim.x;
    for (size_t i = blockIdx.x * blockDim.x + threadIdx.x; i < n4; i += stride) {
        float4 v = ((const float4*)src)[i];
        __half2 h0 = __floats2half2_rn(v.x, v.y);
        __half2 h1 = __floats2half2_rn(v.z, v.w);
        uint2 u = make_uint2(*(uint32_t*)&h0, *(uint32_t*)&h1);
        ((uint2*)dst)[i] = u;
    }
}

// ---------------- stage 2: router (+ x fp16 convert) -------------------------
__global__ void router_kernel(const float* __restrict__ x,
                              const float* __restrict__ Wr) {
    const int t = blockIdx.x;
    __shared__ float sx[HD];
    __shared__ float slog[NE];

    const float* xr = x + (size_t)t * HD;
    for (int i = threadIdx.x; i < HD; i += blockDim.x) {
        const float v = xr[i];
        sx[i] = v;
        g_xh[(size_t)t * HD + i] = __float2half_rn(v);
    }
    __syncthreads();

    const int w = threadIdx.x >> 5, lane = threadIdx.x & 31;
    if (w < NE) {
        const float* wr = Wr + (size_t)w * HD;
        float s = 0.f;
        for (int i = lane; i < HD; i += 32) s += sx[i] * wr[i];
        #pragma unroll
        for (int o = 16; o > 0; o >>= 1) s += __shfl_xor_sync(0xffffffffu, s, o);
        if (lane == 0) slog[w] = s;
    }
    __syncthreads();

    if (threadIdx.x == 0) {
        int i0 = 0; float v0 = slog[0];
        #pragma unroll
        for (int e = 1; e < NE; e++) if (slog[e] > v0) { v0 = slog[e]; i0 = e; }
        int i1 = -1; float v1 = -INFINITY;
        #pragma unroll
        for (int e = 0; e < NE; e++) {
            if (e == i0) continue;
            if (slog[e] > v1) { v1 = slog[e]; i1 = e; }
        }
        float e1 = expf(v1 - v0);
        float inv = 1.f / (1.f + e1);
        g_expert_of_tok[t * 2 + 0] = i0; g_gate_of_tok[t * 2 + 0] = inv;
        g_expert_of_tok[t * 2 + 1] = i1; g_gate_of_tok[t * 2 + 1] = e1 * inv;
        atomicAdd(&g_counts[i0], 1);
        atomicAdd(&g_counts[i1], 1);
    }
}

// ---------------- stage 3: compaction (offsets fused) ------------------------
__global__ void build_kernel() {
    const int e = blockIdx.x;
    __shared__ int warp_sums[32];
    int base = 0;
    #pragma unroll
    for (int i = 0; i < NE; i++) if (i < e) base += g_counts[i];
    const int lane = threadIdx.x & 31, w = threadIdx.x >> 5;

    for (int t0 = 0; t0 < NTOK; t0 += 1024) {
        const int t = t0 + threadIdx.x;
        int k = -1;
        if (g_expert_of_tok[t * 2 + 0] == e) k = 0;
        else if (g_expert_of_tok[t * 2 + 1] == e) k = 1;
        const int flag = (k >= 0) ? 1 : 0;

        const unsigned bal = __ballot_sync(0xffffffffu, flag);
        const int pre = __popc(bal & ((1u << lane) - 1u));
        if (lane == 0) warp_sums[w] = __popc(bal);
        __syncthreads();
        int woff = 0, total = 0;
        #pragma unroll
        for (int i = 0; i < 32; i++) {
            if (i < w) woff += warp_sums[i];
            total += warp_sums[i];
        }
        if (flag) {
            const int slot = base + woff + pre;
            g_tok_of_slot[slot] = t;
            g_slot_of_tok[t * 2 + k] = slot;
        }
        base += total;
        __syncthreads();
    }
}

// ---------------- stage 4/5: routed fp16 GEMM, cp.async 4-stage --------------
// FIRST=true : g_h(fp16) = gelu(g_xh[gather] @ W1h[e] + b1[e])   K=HD,  N=FD
// FIRST=false: g_y(fp32) = g_h[contig] @ W2h[e]                  K=FD,  N=HD
template <bool FIRST>
__global__ __launch_bounds__(256, 1) void moe_mma(const float* __restrict__ bias) {
    constexpr int KDIM = FIRST ? HD : FD;
    constexpr int NDIM = FIRST ? FD : HD;
    constexpr int NKT  = KDIM / BK;

    const int e  = blockIdx.z;
    const int ne = g_counts[e];
    const int m0 = blockIdx.y * BM;
    if (m0 >= ne) return;
    const int n0 = blockIdx.x * BN;
    int off = 0;
    #pragma unroll
    for (int i = 0; i < NE; i++) if (i < e) off += g_counts[i];

    extern __shared__ char smem[];
    const uint32_t sb = smem_u32(smem);
    const int tid = threadIdx.x;

    if (FIRST && tid < 64)
        ((float4*)(smem + SM_BIAS))[tid] =
            ((const float4*)(bias + (size_t)e * NDIM + n0))[tid];

    const __half* Ab = FIRST ? g_xh : g_h;
    const __half* Wb = (FIRST ? g_w1h : g_w2h) + (size_t)e * KDIM * NDIM;

    // ---- cp.async staging maps ----
    // A: thread -> row r = tid>>1, 32B chunk hs = tid&1 (granules hs*2, hs*2+1)
    const int r = tid >> 1, hs = tid & 1;
    int ga = m0 + r; if (ga > ne - 1) ga = ne - 1;
    const int rowid = FIRST ? g_tok_of_slot[off + ga] : (off + ga);
    const __half* asrc = Ab + (size_t)rowid * KDIM + hs * 16;
    const int g0 = hs * 2;
    const uint32_t ad0 = (uint32_t)(r * 64 + (((g0 + 0) ^ ((r >> 1) & 3)) * 16));
    const uint32_t ad1 = (uint32_t)(r * 64 + (((g0 + 1) ^ ((r >> 1) & 3)) * 16));

    // B: thread -> k-row kk = tid>>3, lane8 = tid&7, granules lane8 + 8j
    const int kk = tid >> 3, lane8 = tid & 7;
    const __half* bsrc = Wb + (size_t)kk * NDIM + n0 + lane8 * 8;
    uint32_t bd[4];
    #pragma unroll
    for (int j = 0; j < 4; j++)
        bd[j] = (uint32_t)(kk * 512 + (((lane8 + 8 * j) ^ (kk & 7)) * 16));

    // ---- ldmatrix fragment maps: warp grid 2(M) x 4(N) ----
    const int w = tid >> 5, lane = tid & 31;
    const int wm = w & 1, wn = w >> 1;
    const int l16 = lane & 15, lh = lane >> 4;
    uint32_t ao[2][4], bo[2][4];
    #pragma unroll
    for (int ks = 0; ks < 2; ks++) {
        #pragma unroll
        for (int mi = 0; mi < 4; mi++) {
            const int row = wm * 64 + mi * 16 + l16;
            const int gr  = ks * 2 + lh;
            ao[ks][mi] = (uint32_t)(row * 64 + ((gr ^ ((row >> 1) & 3)) * 16));
        }
        #pragma unroll
        for (int np = 0; np < 4; np++) {
            const int kr = ks * 16 + l16;
            const int ng = wn * 8 + np * 2 + lh;
            bo[ks][np] = (uint32_t)(kr * 512 + ((ng ^ (kr & 7)) * 16));
        }
    }

    float acc[4][8][4];
    #pragma unroll
    for (int mi = 0; mi < 4; mi++)
        #pragma unroll
        for (int ni = 0; ni < 8; ni++)
            #pragma unroll
            for (int q = 0; q < 4; q++) acc[mi][ni][q] = 0.f;

    auto issue_stage = [&](int kt) {
        const uint32_t sa  = sb + SM_A + (kt & (STAGES - 1)) * 8192;
        const uint32_t sbm = sb + SM_B + (kt & (STAGES - 1)) * 16384;
        const __half* ap = asrc + (size_t)kt * BK;
        cp16(sa + ad0, ap);
        cp16(sa + ad1, ap + 8);
        const __half* bp = bsrc + (size_t)kt * BK * NDIM;
        #pragma unroll
        for (int j = 0; j < 4; j++) cp16(sbm + bd[j], bp + 64 * j);
    };

    // ---- prologue: fill 3 stages ----
    #pragma unroll
    for (int s = 0; s < STAGES - 1; s++) { issue_stage(s); cp_commit(); }

    // ---- mainloop ----
    #pragma unroll 1
    for (int kt = 0; kt < NKT; kt++) {
        cp_wait2();
        __syncthreads();

        const int buf = kt & (STAGES - 1);
        const uint32_t sA = sb + SM_A + buf * 8192;
        const uint32_t sB = sb + SM_B + buf * 16384;
        #pragma unroll
        for (int ks = 0; ks < 2; ks++) {
            uint32_t af[4][4];
            #pragma unroll
            for (int mi = 0; mi < 4; mi++) ldsm4(af[mi], sA + ao[ks][mi]);
            #pragma unroll
            for (int np = 0; np < 4; np++) {
                uint32_t bf[4];
                ldsm4t(bf, sB + bo[ks][np]);
                #pragma unroll
                for (int mi = 0; mi < 4; mi++) {
                    mma16816(acc[mi][np * 2 + 0], af[mi], bf[0], bf[1]);
                    mma16816(acc[mi][np * 2 + 1], af[mi], bf[2], bf[3]);
                }
            }
        }

        if (kt + STAGES - 1 < NKT) issue_stage(kt + STAGES - 1);
        cp_commit();
    }

    // ---- epilogue ----
    const int rbase = wm * 64 + (lane >> 2);
    const int cbase = wn * 64 + (lane & 3) * 2;
    #pragma unroll
    for (int mi = 0; mi < 4; mi++) {
        #pragma unroll
        for (int hrow = 0; hrow < 2; hrow++) {
            const int mloc = rbase + mi * 16 + hrow * 8;
            const int grow = m0 + mloc;
            if (grow >= ne) continue;
            #pragma unroll
            for (int ni = 0; ni < 8; ni++) {
                const int cr = cbase + ni * 8;
                float v0 = acc[mi][ni][hrow * 2 + 0];
                float v1 = acc[mi][ni][hrow * 2 + 1];
                if (FIRST) {
                    const float2 bv = *(const float2*)(smem + SM_BIAS + cr * 4);
                    v0 = gelu_exact(v0 + bv.x);
                    v1 = gelu_exact(v1 + bv.y);
                    __half2 hv = __floats2half2_rn(v0, v1);
                    *(__half2*)(g_h + (size_t)(off + grow) * NDIM + n0 + cr) = hv;
                } else {
                    *(float2*)(g_y + (size_t)(off + grow) * NDIM + n0 + cr) =
                        make_float2(v0, v1);
                }
            }
        }
    }
}

// ---------------- stage 6: gated combine -------------------------------------
__global__ void combine_kernel(const float* __restrict__ b2,
                               float* __restrict__ out) {
    const int t  = blockIdx.x;
    const int e0 = g_expert_of_tok[t * 2 + 0], e1 = g_expert_of_tok[t * 2 + 1];
    const float gg0 = g_gate_of_tok[t * 2 + 0], gg1 = g_gate_of_tok[t * 2 + 1];
    const int s0 = g_slot_of_tok[t * 2 + 0], s1 = g_slot_of_tok[t * 2 + 1];

    const float4* y0  = (const float4*)(g_y + (size_t)s0 * HD);
    const float4* y1  = (const float4*)(g_y + (size_t)s1 * HD);
    const float4* bb0 = (const float4*)(b2 + (size_t)e0 * HD);
    const float4* bb1 = (const float4*)(b2 + (size_t)e1 * HD);
    float4* o = (float4*)(out + (size_t)t * HD);

    for (int i = threadIdx.x; i < HD / 4; i += blockDim.x) {
        const float4 a = y0[i], b = y1[i], c = bb0[i], d = bb1[i];
        float4 rr;
        rr.x = gg0 * (a.x + c.x) + gg1 * (b.x + d.x);
        rr.y = gg0 * (a.y + c.y) + gg1 * (b.y + d.y);
        rr.z = gg0 * (a.z + c.z) + gg1 * (b.z + d.z);
        rr.w = gg0 * (a.w + c.w) + gg1 * (b.w + d.w);
        o[i] = rr;
    }
}

// ---------------- launch ------------------------------------------------------
extern "C" void kernel_launch(void* const* d_in, const int* in_sizes, int n_in,
                              void* d_out, int out_size) {
    const float* x  = (const float*)d_in[0];
    const float* Wr = (const float*)d_in[1];
    const float* W1 = (const float*)d_in[2];
    const float* b1 = (const float*)d_in[3];
    const float* W2 = (const float*)d_in[4];
    const float* b2 = (const float*)d_in[5];
    float* out = (float*)d_out;

    cudaFuncSetAttribute(moe_mma<true>,  cudaFuncAttributeMaxDynamicSharedMemorySize, SMEM_BYTES);
    cudaFuncSetAttribute(moe_mma<false>, cudaFuncAttributeMaxDynamicSharedMemorySize, SMEM_BYTES);

    cvt_kernel<<<dim3(1024, 2), 256>>>(W1, W2);
    router_kernel<<<NTOK, 256>>>(x, Wr);
    build_kernel<<<NE, 1024>>>();
    moe_mma<true><<<dim3(FD / BN, NSLOT / BM, NE), 256, SMEM_BYTES>>>(b1);
    moe_mma<false><<<dim3(HD / BN, NSLOT / BM, NE), 256, SMEM_BYTES>>>(nullptr);
    combine_kernel<<<NTOK, 256>>>(b2, out);
}

// round 6
// speedup vs baseline: 2.2364x; 1.0049x over previous
#include <cuda_runtime.h>
#include <cuda_fp16.h>
#include <math.h>
#include <stdint.h>

// ---------------- problem constants -----------------------------------------
#define NTOK 4096
#define HD   1024
#define NE   8
#define FD   4096
#define NSLOT (NTOK * 2)

// ---------------- GEMM tiling (fp16 mma.sync + ldmatrix + cp.async) ----------
#define BM 128
#define BN 256
#define BK 32
#define STAGES 4
#define NTHR 512

// dynamic smem layout (bytes)
#define SM_A    0                      // STAGES x 128x32 fp16 = 4 x 8192
#define SM_B    (STAGES * 8192)        // STAGES x 32x256 fp16 = 4 x 16384
#define SM_BIAS (SM_A + STAGES * 8192 + STAGES * 16384)   // 98304
#define SMEM_BYTES (SM_BIAS + 1024)    // 99328

// ---------------- scratch (device globals; no allocations) -------------------
__device__ __align__(128) __half g_xh[(size_t)NTOK * HD];
__device__ __align__(128) __half g_w1h[(size_t)NE * HD * FD];
__device__ __align__(128) __half g_w2h[(size_t)NE * FD * HD];
__device__ __align__(128) __half g_h[(size_t)NSLOT * FD];
__device__ float  g_y[(size_t)NSLOT * HD];
__device__ int    g_tok_of_slot[NSLOT];
__device__ int    g_slot_of_tok[NSLOT];
__device__ int    g_expert_of_tok[NSLOT];
__device__ float  g_gate_of_tok[NSLOT];
__device__ int    g_counts[NE];

// ---------------- helpers ----------------------------------------------------
__device__ __forceinline__ uint32_t smem_u32(const void* p) {
    uint32_t a;
    asm("{ .reg .u64 t; cvta.to.shared.u64 t, %1; cvt.u32.u64 %0, t; }" : "=r"(a) : "l"(p));
    return a;
}

__device__ __forceinline__ void cp16(uint32_t dst, const void* src) {
    asm volatile("cp.async.cg.shared.global [%0], [%1], 16;" :: "r"(dst), "l"(src));
}
__device__ __forceinline__ void cp_commit() {
    asm volatile("cp.async.commit_group;" ::: "memory");
}
__device__ __forceinline__ void cp_wait2() {
    asm volatile("cp.async.wait_group 2;" ::: "memory");
}

__device__ __forceinline__ void ldsm4(uint32_t r[4], uint32_t addr) {
    asm volatile("ldmatrix.sync.aligned.m8n8.x4.shared.b16 {%0,%1,%2,%3}, [%4];"
                 : "=r"(r[0]), "=r"(r[1]), "=r"(r[2]), "=r"(r[3]) : "r"(addr));
}
__device__ __forceinline__ void ldsm4t(uint32_t r[4], uint32_t addr) {
    asm volatile("ldmatrix.sync.aligned.m8n8.x4.trans.shared.b16 {%0,%1,%2,%3}, [%4];"
                 : "=r"(r[0]), "=r"(r[1]), "=r"(r[2]), "=r"(r[3]) : "r"(addr));
}

__device__ __forceinline__ void mma16816(float c[4], const uint32_t a[4],
                                         uint32_t b0, uint32_t b1) {
    asm volatile(
        "mma.sync.aligned.m16n8k16.row.col.f32.f16.f16.f32 "
        "{%0,%1,%2,%3}, {%4,%5,%6,%7}, {%8,%9}, {%0,%1,%2,%3};\n"
        : "+f"(c[0]), "+f"(c[1]), "+f"(c[2]), "+f"(c[3])
        : "r"(a[0]), "r"(a[1]), "r"(a[2]), "r"(a[3]), "r"(b0), "r"(b1));
}

__device__ __forceinline__ float gelu_exact(float x) {
    return 0.5f * x * (1.0f + erff(x * 0.70710678118654752440f));
}

// ---------------- stage 1: weight fp16 pre-convert (+zero counts) ------------
__global__ void cvt_kernel(const float* __restrict__ W1,
                           const float* __restrict__ W2) {
    if (blockIdx.x == 0 && blockIdx.y == 0 && threadIdx.x < NE)
        g_counts[threadIdx.x] = 0;
    const float* src = blockIdx.y ? W2 : W1;
    __half* dst = blockIdx.y ? g_w2h : g_w1h;
    const size_t n4 = (size_t)NE * HD * FD / 4;
    const size_t stride = (size_t)gridDim.x * blockDim.x;
    for (size_t i = blockIdx.x * blockDim.x + threadIdx.x; i < n4; i += stride) {
        float4 v = ((const float4*)src)[i];
        __half2 h0 = __floats2half2_rn(v.x, v.y);
        __half2 h1 = __floats2half2_rn(v.z, v.w);
        uint2 u = make_uint2(*(uint32_t*)&h0, *(uint32_t*)&h1);
        ((uint2*)dst)[i] = u;
    }
}

// ---------------- stage 2: router (+ x fp16 convert) -------------------------
__global__ void router_kernel(const float* __restrict__ x,
                              const float* __restrict__ Wr) {
    const int t = blockIdx.x;
    __shared__ float sx[HD];
    __shared__ float slog[NE];

    const float* xr = x + (size_t)t * HD;
    for (int i = threadIdx.x; i < HD; i += blockDim.x) {
        const float v = xr[i];
        sx[i] = v;
        g_xh[(size_t)t * HD + i] = __float2half_rn(v);
    }
    __syncthreads();

    const int w = threadIdx.x >> 5, lane = threadIdx.x & 31;
    if (w < NE) {
        const float* wr = Wr + (size_t)w * HD;
        float s = 0.f;
        for (int i = lane; i < HD; i += 32) s += sx[i] * wr[i];
        #pragma unroll
        for (int o = 16; o > 0; o >>= 1) s += __shfl_xor_sync(0xffffffffu, s, o);
        if (lane == 0) slog[w] = s;
    }
    __syncthreads();

    if (threadIdx.x == 0) {
        int i0 = 0; float v0 = slog[0];
        #pragma unroll
        for (int e = 1; e < NE; e++) if (slog[e] > v0) { v0 = slog[e]; i0 = e; }
        int i1 = -1; float v1 = -INFINITY;
        #pragma unroll
        for (int e = 0; e < NE; e++) {
            if (e == i0) continue;
            if (slog[e] > v1) { v1 = slog[e]; i1 = e; }
        }
        float e1 = expf(v1 - v0);
        float inv = 1.f / (1.f + e1);
        g_expert_of_tok[t * 2 + 0] = i0; g_gate_of_tok[t * 2 + 0] = inv;
        g_expert_of_tok[t * 2 + 1] = i1; g_gate_of_tok[t * 2 + 1] = e1 * inv;
        atomicAdd(&g_counts[i0], 1);
        atomicAdd(&g_counts[i1], 1);
    }
}

// ---------------- stage 3: compaction (offsets fused) ------------------------
__global__ void build_kernel() {
    const int e = blockIdx.x;
    __shared__ int warp_sums[32];
    int base = 0;
    #pragma unroll
    for (int i = 0; i < NE; i++) if (i < e) base += g_counts[i];
    const int lane = threadIdx.x & 31, w = threadIdx.x >> 5;

    for (int t0 = 0; t0 < NTOK; t0 += 1024) {
        const int t = t0 + threadIdx.x;
        int k = -1;
        if (g_expert_of_tok[t * 2 + 0] == e) k = 0;
        else if (g_expert_of_tok[t * 2 + 1] == e) k = 1;
        const int flag = (k >= 0) ? 1 : 0;

        const unsigned bal = __ballot_sync(0xffffffffu, flag);
        const int pre = __popc(bal & ((1u << lane) - 1u));
        if (lane == 0) warp_sums[w] = __popc(bal);
        __syncthreads();
        int woff = 0, total = 0;
        #pragma unroll
        for (int i = 0; i < 32; i++) {
            if (i < w) woff += warp_sums[i];
            total += warp_sums[i];
        }
        if (flag) {
            const int slot = base + woff + pre;
            g_tok_of_slot[slot] = t;
            g_slot_of_tok[t * 2 + k] = slot;
        }
        base += total;
        __syncthreads();
    }
}

// ---------------- stage 4/5: routed fp16 GEMM, 512 threads, 16 warps ---------
// FIRST=true : g_h(fp16) = gelu(g_xh[gather] @ W1h[e] + b1[e])   K=HD,  N=FD
// FIRST=false: g_y(fp32) = g_h[contig] @ W2h[e]                  K=FD,  N=HD
template <bool FIRST>
__global__ __launch_bounds__(NTHR, 1) void moe_mma(const float* __restrict__ bias) {
    constexpr int KDIM = FIRST ? HD : FD;
    constexpr int NDIM = FIRST ? FD : HD;
    constexpr int NKT  = KDIM / BK;

    const int e  = blockIdx.z;
    const int ne = g_counts[e];
    const int m0 = blockIdx.y * BM;
    if (m0 >= ne) return;
    const int n0 = blockIdx.x * BN;
    int off = 0;
    #pragma unroll
    for (int i = 0; i < NE; i++) if (i < e) off += g_counts[i];

    extern __shared__ char smem[];
    const uint32_t sb = smem_u32(smem);
    const int tid = threadIdx.x;

    if (FIRST && tid < 64)
        ((float4*)(smem + SM_BIAS))[tid] =
            ((const float4*)(bias + (size_t)e * NDIM + n0))[tid];

    const __half* Ab = FIRST ? g_xh : g_h;
    const __half* Wb = (FIRST ? g_w1h : g_w2h) + (size_t)e * KDIM * NDIM;

    // ---- cp.async staging maps ----
    // A: 512 granules of 16B; thread -> row r = tid>>2, granule hs = tid&3
    const int r = tid >> 2, hs = tid & 3;
    int ga = m0 + r; if (ga > ne - 1) ga = ne - 1;
    const int rowid = FIRST ? g_tok_of_slot[off + ga] : (off + ga);
    const __half* asrc = Ab + (size_t)rowid * KDIM + hs * 8;
    const uint32_t ad0 = (uint32_t)(r * 64 + ((hs ^ ((r >> 1) & 3)) * 16));

    // B: 1024 granules; thread -> k-row kk = tid>>4, lane16 = tid&15, g = lane16+16j
    const int kk = tid >> 4, lane16 = tid & 15;
    const __half* bsrc = Wb + (size_t)kk * NDIM + n0 + lane16 * 8;
    uint32_t bd[2];
    #pragma unroll
    for (int j = 0; j < 2; j++)
        bd[j] = (uint32_t)(kk * 512 + (((lane16 + 16 * j) ^ (kk & 7)) * 16));

    // ---- ldmatrix fragment maps: warp grid 4(M) x 4(N), warp tile 32x64 ----
    const int w = tid >> 5, lane = tid & 31;
    const int wm = w & 3, wn = w >> 2;
    const int l16 = lane & 15, lh = lane >> 4;
    uint32_t ao[2][2], bo[2][4];
    #pragma unroll
    for (int ks = 0; ks < 2; ks++) {
        #pragma unroll
        for (int mi = 0; mi < 2; mi++) {
            const int row = wm * 32 + mi * 16 + l16;
            const int gr  = ks * 2 + lh;
            ao[ks][mi] = (uint32_t)(row * 64 + ((gr ^ ((row >> 1) & 3)) * 16));
        }
        #pragma unroll
        for (int np = 0; np < 4; np++) {
            const int kr = ks * 16 + l16;
            const int ng = wn * 8 + np * 2 + lh;
            bo[ks][np] = (uint32_t)(kr * 512 + ((ng ^ (kr & 7)) * 16));
        }
    }

    float acc[2][8][4];
    #pragma unroll
    for (int mi = 0; mi < 2; mi++)
        #pragma unroll
        for (int ni = 0; ni < 8; ni++)
            #pragma unroll
            for (int q = 0; q < 4; q++) acc[mi][ni][q] = 0.f;

    auto issue_stage = [&](int kt) {
        const uint32_t sa  = sb + SM_A + (kt & (STAGES - 1)) * 8192;
        const uint32_t sbm = sb + SM_B + (kt & (STAGES - 1)) * 16384;
        cp16(sa + ad0, asrc + (size_t)kt * BK);
        const __half* bp = bsrc + (size_t)kt * BK * NDIM;
        cp16(sbm + bd[0], bp);
        cp16(sbm + bd[1], bp + 128);
    };

    // ---- prologue: fill 3 stages ----
    #pragma unroll
    for (int s = 0; s < STAGES - 1; s++) { issue_stage(s); cp_commit(); }

    // ---- mainloop ----
    #pragma unroll 1
    for (int kt = 0; kt < NKT; kt++) {
        cp_wait2();
        __syncthreads();

        const int buf = kt & (STAGES - 1);
        const uint32_t sA = sb + SM_A + buf * 8192;
        const uint32_t sB = sb + SM_B + buf * 16384;
        #pragma unroll
        for (int ks = 0; ks < 2; ks++) {
            // batch all fragment loads for this ks, then stream 16 mma
            uint32_t af[2][4], bf[4][4];
            ldsm4 (af[0], sA + ao[ks][0]);
            ldsm4 (af[1], sA + ao[ks][1]);
            ldsm4t(bf[0], sB + bo[ks][0]);
            ldsm4t(bf[1], sB + bo[ks][1]);
            ldsm4t(bf[2], sB + bo[ks][2]);
            ldsm4t(bf[3], sB + bo[ks][3]);
            #pragma unroll
            for (int np = 0; np < 4; np++) {
                #pragma unroll
                for (int mi = 0; mi < 2; mi++) {
                    mma16816(acc[mi][np * 2 + 0], af[mi], bf[np][0], bf[np][1]);
                    mma16816(acc[mi][np * 2 + 1], af[mi], bf[np][2], bf[np][3]);
                }
            }
        }

        if (kt + STAGES - 1 < NKT) issue_stage(kt + STAGES - 1);
        cp_commit();
    }

    // ---- epilogue ----
    const int rbase = wm * 32 + (lane >> 2);
    const int cbase = wn * 64 + (lane & 3) * 2;
    #pragma unroll
    for (int mi = 0; mi < 2; mi++) {
        #pragma unroll
        for (int hrow = 0; hrow < 2; hrow++) {
            const int mloc = rbase + mi * 16 + hrow * 8;
            const int grow = m0 + mloc;
            if (grow >= ne) continue;
            #pragma unroll
            for (int ni = 0; ni < 8; ni++) {
                const int cr = cbase + ni * 8;
                float v0 = acc[mi][ni][hrow * 2 + 0];
                float v1 = acc[mi][ni][hrow * 2 + 1];
                if (FIRST) {
                    const float2 bv = *(const float2*)(smem + SM_BIAS + cr * 4);
                    v0 = gelu_exact(v0 + bv.x);
                    v1 = gelu_exact(v1 + bv.y);
                    __half2 hv = __floats2half2_rn(v0, v1);
                    *(__half2*)(g_h + (size_t)(off + grow) * NDIM + n0 + cr) = hv;
                } else {
                    *(float2*)(g_y + (size_t)(off + grow) * NDIM + n0 + cr) =
                        make_float2(v0, v1);
                }
            }
        }
    }
}

// ---------------- stage 6: gated combine -------------------------------------
__global__ void combine_kernel(const float* __restrict__ b2,
                               float* __restrict__ out) {
    const int t  = blockIdx.x;
    const int e0 = g_expert_of_tok[t * 2 + 0], e1 = g_expert_of_tok[t * 2 + 1];
    const float gg0 = g_gate_of_tok[t * 2 + 0], gg1 = g_gate_of_tok[t * 2 + 1];
    const int s0 = g_slot_of_tok[t * 2 + 0], s1 = g_slot_of_tok[t * 2 + 1];

    const float4* y0  = (const float4*)(g_y + (size_t)s0 * HD);
    const float4* y1  = (const float4*)(g_y + (size_t)s1 * HD);
    const float4* bb0 = (const float4*)(b2 + (size_t)e0 * HD);
    const float4* bb1 = (const float4*)(b2 + (size_t)e1 * HD);
    float4* o = (float4*)(out + (size_t)t * HD);

    for (int i = threadIdx.x; i < HD / 4; i += blockDim.x) {
        const float4 a = y0[i], b = y1[i], c = bb0[i], d = bb1[i];
        float4 rr;
        rr.x = gg0 * (a.x + c.x) + gg1 * (b.x + d.x);
        rr.y = gg0 * (a.y + c.y) + gg1 * (b.y + d.y);
        rr.z = gg0 * (a.z + c.z) + gg1 * (b.z + d.z);
        rr.w = gg0 * (a.w + c.w) + gg1 * (b.w + d.w);
        o[i] = rr;
    }
}

// ---------------- launch ------------------------------------------------------
extern "C" void kernel_launch(void* const* d_in, const int* in_sizes, int n_in,
                              void* d_out, int out_size) {
    const float* x  = (const float*)d_in[0];
    const float* Wr = (const float*)d_in[1];
    const float* W1 = (const float*)d_in[2];
    const float* b1 = (const float*)d_in[3];
    const float* W2 = (const float*)d_in[4];
    const float* b2 = (const float*)d_in[5];
    float* out = (float*)d_out;

    cudaFuncSetAttribute(moe_mma<true>,  cudaFuncAttributeMaxDynamicSharedMemorySize, SMEM_BYTES);
    cudaFuncSetAttribute(moe_mma<false>, cudaFuncAttributeMaxDynamicSharedMemorySize, SMEM_BYTES);

    cvt_kernel<<<dim3(1024, 2), 256>>>(W1, W2);
    router_kernel<<<NTOK, 256>>>(x, Wr);
    build_kernel<<<NE, 1024>>>();
    moe_mma<true><<<dim3(FD / BN, NSLOT / BM, NE), NTHR, SMEM_BYTES>>>(b1);
    moe_mma<false><<<dim3(HD / BN, NSLOT / BM, NE), NTHR, SMEM_BYTES>>>(nullptr);
    combine_kernel<<<NTOK, 256>>>(b2, out);
}

// round 7
// speedup vs baseline: 2.4267x; 1.0851x over previous
#include <cuda_runtime.h>
#include <cuda_fp16.h>
#include <math.h>
#include <stdint.h>

// ---------------- problem constants -----------------------------------------
#define NTOK 4096
#define HD   1024
#define NE   8
#define FD   4096
#define NSLOT (NTOK * 2)

// ---------------- GEMM tiling (fp16 mma.sync + ldmatrix + cp.async) ----------
#define BM 128
#define BN 128
#define BK 32
#define STAGES 4
#define NTHR 256

// dynamic smem layout (bytes); stage = A 8KB + B 8KB
#define SM_A    0                       // STAGES x 128x32 fp16 = 4 x 8192
#define SM_B    (STAGES * 8192)         // STAGES x 32x128 fp16 = 4 x 8192
#define SM_BIAS (SM_B + STAGES * 8192)  // 65536 ; 128 fp32
#define SMEM_BYTES (SM_BIAS + 512)      // 66048  (2 CTAs/SM -> 132KB)

// ---------------- scratch (device globals; no allocations) -------------------
__device__ __align__(128) __half g_xh[(size_t)NTOK * HD];
__device__ __align__(128) __half g_w1h[(size_t)NE * HD * FD];
__device__ __align__(128) __half g_w2h[(size_t)NE * FD * HD];
__device__ __align__(128) __half g_h[(size_t)NSLOT * FD];
__device__ float  g_y[(size_t)NSLOT * HD];
__device__ int    g_tok_of_slot[NSLOT];
__device__ int    g_slot_of_tok[NSLOT];
__device__ int    g_expert_of_tok[NSLOT];
__device__ float  g_gate_of_tok[NSLOT];
__device__ int    g_counts[NE];

// ---------------- helpers ----------------------------------------------------
__device__ __forceinline__ uint32_t smem_u32(const void* p) {
    uint32_t a;
    asm("{ .reg .u64 t; cvta.to.shared.u64 t, %1; cvt.u32.u64 %0, t; }" : "=r"(a) : "l"(p));
    return a;
}

__device__ __forceinline__ void cp16(uint32_t dst, const void* src) {
    asm volatile("cp.async.cg.shared.global [%0], [%1], 16;" :: "r"(dst), "l"(src));
}
__device__ __forceinline__ void cp_commit() {
    asm volatile("cp.async.commit_group;" ::: "memory");
}
__device__ __forceinline__ void cp_wait2() {
    asm volatile("cp.async.wait_group 2;" ::: "memory");
}

__device__ __forceinline__ void ldsm4(uint32_t r[4], uint32_t addr) {
    asm volatile("ldmatrix.sync.aligned.m8n8.x4.shared.b16 {%0,%1,%2,%3}, [%4];"
                 : "=r"(r[0]), "=r"(r[1]), "=r"(r[2]), "=r"(r[3]) : "r"(addr));
}
__device__ __forceinline__ void ldsm4t(uint32_t r[4], uint32_t addr) {
    asm volatile("ldmatrix.sync.aligned.m8n8.x4.trans.shared.b16 {%0,%1,%2,%3}, [%4];"
                 : "=r"(r[0]), "=r"(r[1]), "=r"(r[2]), "=r"(r[3]) : "r"(addr));
}

__device__ __forceinline__ void mma16816(float c[4], const uint32_t a[4],
                                         uint32_t b0, uint32_t b1) {
    asm volatile(
        "mma.sync.aligned.m16n8k16.row.col.f32.f16.f16.f32 "
        "{%0,%1,%2,%3}, {%4,%5,%6,%7}, {%8,%9}, {%0,%1,%2,%3};\n"
        : "+f"(c[0]), "+f"(c[1]), "+f"(c[2]), "+f"(c[3])
        : "r"(a[0]), "r"(a[1]), "r"(a[2]), "r"(a[3]), "r"(b0), "r"(b1));
}

__device__ __forceinline__ float gelu_exact(float x) {
    return 0.5f * x * (1.0f + erff(x * 0.70710678118654752440f));
}

// ---------------- stage 1: weight fp16 pre-convert (+zero counts) ------------
__global__ void cvt_kernel(const float* __restrict__ W1,
                           const float* __restrict__ W2) {
    if (blockIdx.x == 0 && blockIdx.y == 0 && threadIdx.x < NE)
        g_counts[threadIdx.x] = 0;
    const float* src = blockIdx.y ? W2 : W1;
    __half* dst = blockIdx.y ? g_w2h : g_w1h;
    const size_t n4 = (size_t)NE * HD * FD / 4;
    const size_t stride = (size_t)gridDim.x * blockDim.x;
    for (size_t i = blockIdx.x * blockDim.x + threadIdx.x; i < n4; i += stride) {
        float4 v = ((const float4*)src)[i];
        __half2 h0 = __floats2half2_rn(v.x, v.y);
        __half2 h1 = __floats2half2_rn(v.z, v.w);
        uint2 u = make_uint2(*(uint32_t*)&h0, *(uint32_t*)&h1);
        ((uint2*)dst)[i] = u;
    }
}

// ---------------- stage 2: router (+ x fp16 convert) -------------------------
__global__ void router_kernel(const float* __restrict__ x,
                              const float* __restrict__ Wr) {
    const int t = blockIdx.x;
    __shared__ float sx[HD];
    __shared__ float slog[NE];

    const float* xr = x + (size_t)t * HD;
    for (int i = threadIdx.x; i < HD; i += blockDim.x) {
        const float v = xr[i];
        sx[i] = v;
        g_xh[(size_t)t * HD + i] = __float2half_rn(v);
    }
    __syncthreads();

    const int w = threadIdx.x >> 5, lane = threadIdx.x & 31;
    if (w < NE) {
        const float* wr = Wr + (size_t)w * HD;
        float s = 0.f;
        for (int i = lane; i < HD; i += 32) s += sx[i] * wr[i];
        #pragma unroll
        for (int o = 16; o > 0; o >>= 1) s += __shfl_xor_sync(0xffffffffu, s, o);
        if (lane == 0) slog[w] = s;
    }
    __syncthreads();

    if (threadIdx.x == 0) {
        int i0 = 0; float v0 = slog[0];
        #pragma unroll
        for (int e = 1; e < NE; e++) if (slog[e] > v0) { v0 = slog[e]; i0 = e; }
        int i1 = -1; float v1 = -INFINITY;
        #pragma unroll
        for (int e = 0; e < NE; e++) {
            if (e == i0) continue;
            if (slog[e] > v1) { v1 = slog[e]; i1 = e; }
        }
        float e1 = expf(v1 - v0);
        float inv = 1.f / (1.f + e1);
        g_expert_of_tok[t * 2 + 0] = i0; g_gate_of_tok[t * 2 + 0] = inv;
        g_expert_of_tok[t * 2 + 1] = i1; g_gate_of_tok[t * 2 + 1] = e1 * inv;
        atomicAdd(&g_counts[i0], 1);
        atomicAdd(&g_counts[i1], 1);
    }
}

// ---------------- stage 3: compaction (offsets fused) ------------------------
__global__ void build_kernel() {
    const int e = blockIdx.x;
    __shared__ int warp_sums[32];
    int base = 0;
    #pragma unroll
    for (int i = 0; i < NE; i++) if (i < e) base += g_counts[i];
    const int lane = threadIdx.x & 31, w = threadIdx.x >> 5;

    for (int t0 = 0; t0 < NTOK; t0 += 1024) {
        const int t = t0 + threadIdx.x;
        int k = -1;
        if (g_expert_of_tok[t * 2 + 0] == e) k = 0;
        else if (g_expert_of_tok[t * 2 + 1] == e) k = 1;
        const int flag = (k >= 0) ? 1 : 0;

        const unsigned bal = __ballot_sync(0xffffffffu, flag);
        const int pre = __popc(bal & ((1u << lane) - 1u));
        if (lane == 0) warp_sums[w] = __popc(bal);
        __syncthreads();
        int woff = 0, total = 0;
        #pragma unroll
        for (int i = 0; i < 32; i++) {
            if (i < w) woff += warp_sums[i];
            total += warp_sums[i];
        }
        if (flag) {
            const int slot = base + woff + pre;
            g_tok_of_slot[slot] = t;
            g_slot_of_tok[t * 2 + k] = slot;
        }
        base += total;
        __syncthreads();
    }
}

// ---------------- stage 4/5: routed fp16 GEMM, 128x128, 2 CTAs/SM ------------
// FIRST=true : g_h(fp16) = gelu(g_xh[gather] @ W1h[e] + b1[e])   K=HD,  N=FD
// FIRST=false: g_y(fp32) = g_h[contig] @ W2h[e]                  K=FD,  N=HD
template <bool FIRST>
__global__ __launch_bounds__(NTHR, 2) void moe_mma(const float* __restrict__ bias) {
    constexpr int KDIM = FIRST ? HD : FD;
    constexpr int NDIM = FIRST ? FD : HD;
    constexpr int NKT  = KDIM / BK;

    const int e  = blockIdx.z;
    const int ne = g_counts[e];
    const int m0 = blockIdx.y * BM;
    if (m0 >= ne) return;
    const int n0 = blockIdx.x * BN;
    int off = 0;
    #pragma unroll
    for (int i = 0; i < NE; i++) if (i < e) off += g_counts[i];

    extern __shared__ char smem[];
    const uint32_t sb = smem_u32(smem);
    const int tid = threadIdx.x;

    if (FIRST && tid < 32)
        ((float4*)(smem + SM_BIAS))[tid] =
            ((const float4*)(bias + (size_t)e * NDIM + n0))[tid];

    const __half* Ab = FIRST ? g_xh : g_h;
    const __half* Wb = (FIRST ? g_w1h : g_w2h) + (size_t)e * KDIM * NDIM;

    // ---- cp.async staging maps ----
    // A: 512 granules of 16B; thread -> row r = tid>>1, granules hs*2, hs*2+1
    const int r = tid >> 1, hs = tid & 1;
    int ga = m0 + r; if (ga > ne - 1) ga = ne - 1;
    const int rowid = FIRST ? g_tok_of_slot[off + ga] : (off + ga);
    const __half* asrc = Ab + (size_t)rowid * KDIM + hs * 16;
    const uint32_t ad0 = (uint32_t)(r * 64 + (((hs * 2 + 0) ^ ((r >> 1) & 3)) * 16));
    const uint32_t ad1 = (uint32_t)(r * 64 + (((hs * 2 + 1) ^ ((r >> 1) & 3)) * 16));

    // B: 512 granules; thread -> k-row kk = tid>>3 (32 rows), granules lane8+8j
    const int kk = tid >> 3, lane8 = tid & 7;
    const __half* bsrc = Wb + (size_t)kk * NDIM + n0 + lane8 * 8;
    uint32_t bd[2];
    #pragma unroll
    for (int j = 0; j < 2; j++)
        bd[j] = (uint32_t)(kk * 256 + (((lane8 + 8 * j) ^ (kk & 7)) * 16));

    // ---- ldmatrix fragment maps: warp grid 2(M) x 4(N), warp tile 64x32 ----
    const int w = tid >> 5, lane = tid & 31;
    const int wm = w & 1, wn = w >> 1;
    const int l16 = lane & 15, lh = lane >> 4;
    uint32_t ao[2][4], bo[2][2];
    #pragma unroll
    for (int ks = 0; ks < 2; ks++) {
        #pragma unroll
        for (int mi = 0; mi < 4; mi++) {
            const int row = wm * 64 + mi * 16 + l16;
            const int gr  = ks * 2 + lh;
            ao[ks][mi] = (uint32_t)(row * 64 + ((gr ^ ((row >> 1) & 3)) * 16));
        }
        #pragma unroll
        for (int nb = 0; nb < 2; nb++) {
            const int kr = ks * 16 + l16;
            const int ng = wn * 4 + nb * 2 + lh;
            bo[ks][nb] = (uint32_t)(kr * 256 + ((ng ^ (kr & 7)) * 16));
        }
    }

    float acc[4][4][4];
    #pragma unroll
    for (int mi = 0; mi < 4; mi++)
        #pragma unroll
        for (int ni = 0; ni < 4; ni++)
            #pragma unroll
            for (int q = 0; q < 4; q++) acc[mi][ni][q] = 0.f;

    auto issue_stage = [&](int kt) {
        const uint32_t sa  = sb + SM_A + (kt & (STAGES - 1)) * 8192;
        const uint32_t sbm = sb + SM_B + (kt & (STAGES - 1)) * 8192;
        const __half* ap = asrc + (size_t)kt * BK;
        cp16(sa + ad0, ap);
        cp16(sa + ad1, ap + 8);
        const __half* bp = bsrc + (size_t)kt * BK * NDIM;
        cp16(sbm + bd[0], bp);
        cp16(sbm + bd[1], bp + 64);
    };

    // ---- prologue: fill 3 stages ----
    #pragma unroll
    for (int s = 0; s < STAGES - 1; s++) { issue_stage(s); cp_commit(); }

    // ---- mainloop ----
    #pragma unroll 1
    for (int kt = 0; kt < NKT; kt++) {
        cp_wait2();
        __syncthreads();

        const int buf = kt & (STAGES - 1);
        const uint32_t sA = sb + SM_A + buf * 8192;
        const uint32_t sB = sb + SM_B + buf * 8192;
        #pragma unroll
        for (int ks = 0; ks < 2; ks++) {
            uint32_t af[4][4], bf[2][4];
            ldsm4 (af[0], sA + ao[ks][0]);
            ldsm4 (af[1], sA + ao[ks][1]);
            ldsm4 (af[2], sA + ao[ks][2]);
            ldsm4 (af[3], sA + ao[ks][3]);
            ldsm4t(bf[0], sB + bo[ks][0]);
            ldsm4t(bf[1], sB + bo[ks][1]);
            #pragma unroll
            for (int nb = 0; nb < 2; nb++) {
                #pragma unroll
                for (int mi = 0; mi < 4; mi++) {
                    mma16816(acc[mi][nb * 2 + 0], af[mi], bf[nb][0], bf[nb][1]);
                    mma16816(acc[mi][nb * 2 + 1], af[mi], bf[nb][2], bf[nb][3]);
                }
            }
        }

        if (kt + STAGES - 1 < NKT) issue_stage(kt + STAGES - 1);
        cp_commit();
    }

    // ---- epilogue ----
    const int rbase = wm * 64 + (lane >> 2);
    const int cbase = wn * 32 + (lane & 3) * 2;
    #pragma unroll
    for (int mi = 0; mi < 4; mi++) {
        #pragma unroll
        for (int hrow = 0; hrow < 2; hrow++) {
            const int mloc = rbase + mi * 16 + hrow * 8;
            const int grow = m0 + mloc;
            if (grow >= ne) continue;
            #pragma unroll
            for (int ni = 0; ni < 4; ni++) {
                const int cr = cbase + ni * 8;
                float v0 = acc[mi][ni][hrow * 2 + 0];
                float v1 = acc[mi][ni][hrow * 2 + 1];
                if (FIRST) {
                    const float2 bv = *(const float2*)(smem + SM_BIAS + cr * 4);
                    v0 = gelu_exact(v0 + bv.x);
                    v1 = gelu_exact(v1 + bv.y);
                    __half2 hv = __floats2half2_rn(v0, v1);
                    *(__half2*)(g_h + (size_t)(off + grow) * NDIM + n0 + cr) = hv;
                } else {
                    *(float2*)(g_y + (size_t)(off + grow) * NDIM + n0 + cr) =
                        make_float2(v0, v1);
                }
            }
        }
    }
}

// ---------------- stage 6: gated combine -------------------------------------
__global__ void combine_kernel(const float* __restrict__ b2,
                               float* __restrict__ out) {
    const int t  = blockIdx.x;
    const int e0 = g_expert_of_tok[t * 2 + 0], e1 = g_expert_of_tok[t * 2 + 1];
    const float gg0 = g_gate_of_tok[t * 2 + 0], gg1 = g_gate_of_tok[t * 2 + 1];
    const int s0 = g_slot_of_tok[t * 2 + 0], s1 = g_slot_of_tok[t * 2 + 1];

    const float4* y0  = (const float4*)(g_y + (size_t)s0 * HD);
    const float4* y1  = (const float4*)(g_y + (size_t)s1 * HD);
    const float4* bb0 = (const float4*)(b2 + (size_t)e0 * HD);
    const float4* bb1 = (const float4*)(b2 + (size_t)e1 * HD);
    float4* o = (float4*)(out + (size_t)t * HD);

    for (int i = threadIdx.x; i < HD / 4; i += blockDim.x) {
        const float4 a = y0[i], b = y1[i], c = bb0[i], d = bb1[i];
        float4 rr;
        rr.x = gg0 * (a.x + c.x) + gg1 * (b.x + d.x);
        rr.y = gg0 * (a.y + c.y) + gg1 * (b.y + d.y);
        rr.z = gg0 * (a.z + c.z) + gg1 * (b.z + d.z);
        rr.w = gg0 * (a.w + c.w) + gg1 * (b.w + d.w);
        o[i] = rr;
    }
}

// ---------------- launch ------------------------------------------------------
extern "C" void kernel_launch(void* const* d_in, const int* in_sizes, int n_in,
                              void* d_out, int out_size) {
    const float* x  = (const float*)d_in[0];
    const float* Wr = (const float*)d_in[1];
    const float* W1 = (const float*)d_in[2];
    const float* b1 = (const float*)d_in[3];
    const float* W2 = (const float*)d_in[4];
    const float* b2 = (const float*)d_in[5];
    float* out = (float*)d_out;

    cudaFuncSetAttribute(moe_mma<true>,  cudaFuncAttributeMaxDynamicSharedMemorySize, SMEM_BYTES);
    cudaFuncSetAttribute(moe_mma<false>, cudaFuncAttributeMaxDynamicSharedMemorySize, SMEM_BYTES);

    cvt_kernel<<<dim3(1024, 2), 256>>>(W1, W2);
    router_kernel<<<NTOK, 256>>>(x, Wr);
    build_kernel<<<NE, 1024>>>();
    moe_mma<true><<<dim3(FD / BN, NSLOT / BM, NE), NTHR, SMEM_BYTES>>>(b1);
    moe_mma<false><<<dim3(HD / BN, NSLOT / BM, NE), NTHR, SMEM_BYTES>>>(nullptr);
    combine_kernel<<<NTOK, 256>>>(b2, out);
}